// round 9
// baseline (speedup 1.0000x reference)
#include <cuda_runtime.h>
#include <cuda_fp16.h>
#include <math.h>

#define N_NODES 50000
#define N_EDGES 800000
#define IN_F    64
#define HEADS   8
#define HID     32
#define CH      256
#define NEG     0.2f
#define NPAD    (N_NODES + 32)

// ---------------- scratch ----------------
__device__ __align__(16) __half g_xh[(size_t)NPAD * IN_F];     // 6.4 MB fp16 x table
__device__ __align__(16) __half g_y[(size_t)NPAD * 512];       // 51 MB normalized per-head agg
__device__ float g_el1[N_NODES * HEADS];
__device__ float g_er1[N_NODES * HEADS];
__device__ float g_feat2[N_NODES];
__device__ int   g_deg[N_NODES];
__device__ int   g_off[N_NODES];
__device__ int   g_rank[N_EDGES];
__device__ int   g_csr_src[N_EDGES];

// ---------------- CSR construction ----------------
__global__ void k_zero_deg() {
    int i = blockIdx.x * blockDim.x + threadIdx.x;
    if (i < N_NODES) g_deg[i] = 0;
}

__global__ void k_count(const int* __restrict__ dst) {
    int i = (blockIdx.x * blockDim.x + threadIdx.x) * 4;
    if (i + 3 < N_EDGES) {
        int4 d = *(const int4*)(dst + i);
        int4 r;
        r.x = atomicAdd(&g_deg[d.x], 1);
        r.y = atomicAdd(&g_deg[d.y], 1);
        r.z = atomicAdd(&g_deg[d.z], 1);
        r.w = atomicAdd(&g_deg[d.w], 1);
        *(int4*)(g_rank + i) = r;
    } else {
        for (int e = i; e < N_EDGES; ++e)
            g_rank[e] = atomicAdd(&g_deg[dst[e]], 1);
    }
}

__global__ void k_scan() {
    __shared__ int sums[1024];
    const int t = threadIdx.x;
    const int chunk = (N_NODES + 1023) / 1024;
    int begin = t * chunk;
    int end = begin + chunk; if (end > N_NODES) end = N_NODES;
    int s = 0;
    for (int i = begin; i < end; ++i) s += g_deg[i];
    sums[t] = s;
    __syncthreads();
    for (int ofs = 1; ofs < 1024; ofs <<= 1) {
        int v = (t >= ofs) ? sums[t - ofs] : 0;
        __syncthreads();
        sums[t] += v;
        __syncthreads();
    }
    int run = (t == 0) ? 0 : sums[t - 1];
    for (int i = begin; i < end; ++i) {
        g_off[i] = run;
        run += g_deg[i];
    }
}

__global__ void k_fill(const int* __restrict__ src, const int* __restrict__ dst) {
    int i = (blockIdx.x * blockDim.x + threadIdx.x) * 4;
    if (i + 3 < N_EDGES) {
        int4 d = *(const int4*)(dst + i);
        int4 s = *(const int4*)(src + i);
        int4 r = *(const int4*)(g_rank + i);
        g_csr_src[g_off[d.x] + r.x] = s.x;
        g_csr_src[g_off[d.y] + r.y] = s.y;
        g_csr_src[g_off[d.z] + r.z] = s.z;
        g_csr_src[g_off[d.w] + r.w] = s.w;
    } else {
        for (int e = i; e < N_EDGES; ++e)
            g_csr_src[g_off[dst[e]] + g_rank[e]] = src[e];
    }
}

// ---------------- prep: fp16 x table + el/er logits --------------------------
// 256 threads, 32 nodes/block. Al = W.al computed per block (cheap, avoids launch).
__global__ void k_prep(const float* __restrict__ x, const float* __restrict__ W,
                       const float* __restrict__ al, const float* __restrict__ ar) {
    __shared__ float xs[32][68];          // 68 pad: float4-aligned rows, conflict-free
    __shared__ float sAl[IN_F][9], sAr[IN_F][9];
    const int tid = threadIdx.x;
    const int n0 = blockIdx.x * 32;
    // load x rows (512 float4)
    #pragma unroll
    for (int r = 0; r < 2; ++r) {
        int e = tid + r * 256;
        int n = e >> 4, i4 = e & 15;
        int node = n0 + n;
        float4 v = (node < N_NODES) ? ((const float4*)(x + (size_t)node * IN_F))[i4]
                                    : make_float4(0.f, 0.f, 0.f, 0.f);
        *(float4*)&xs[n][i4 * 4] = v;
    }
    // project Al/Ar in-block (each thread: 2 entries, 32-FMA dots)
    #pragma unroll
    for (int r = 0; r < 2; ++r) {
        int e = tid + r * 256;
        int i = e >> 3, h = e & 7;
        float sl = 0.f, sr = 0.f;
        #pragma unroll 8
        for (int o = 0; o < HID; ++o) {
            float w = W[i * CH + h * HID + o];
            sl = fmaf(w, al[h * HID + o], sl);
            sr = fmaf(w, ar[h * HID + o], sr);
        }
        sAl[i][h] = sl;
        sAr[i][h] = sr;
    }
    __syncthreads();

    // el/er: thread t = (node t>>3, head t&7)
    {
        const int nn = tid >> 3, h = tid & 7;
        const float4* xr = (const float4*)xs[nn];
        float sl = 0.f, sr = 0.f;
        #pragma unroll
        for (int i4 = 0; i4 < 16; ++i4) {
            float4 xv = xr[i4];
            sl = fmaf(xv.x, sAl[4*i4+0][h], sl); sr = fmaf(xv.x, sAr[4*i4+0][h], sr);
            sl = fmaf(xv.y, sAl[4*i4+1][h], sl); sr = fmaf(xv.y, sAr[4*i4+1][h], sr);
            sl = fmaf(xv.z, sAl[4*i4+2][h], sl); sr = fmaf(xv.z, sAr[4*i4+2][h], sr);
            sl = fmaf(xv.w, sAl[4*i4+3][h], sl); sr = fmaf(xv.w, sAr[4*i4+3][h], sr);
        }
        int node = n0 + nn;
        if (node < N_NODES) {
            g_el1[node * 8 + h] = sl;
            g_er1[node * 8 + h] = sr;
        }
    }
    // write fp16 x table: thread t = (node t>>3, seg t&7): 8 halves (16 B)
    {
        const int nn = tid >> 3, seg = tid & 7;
        float4 a = *(const float4*)&xs[nn][seg * 8];
        float4 b = *(const float4*)&xs[nn][seg * 8 + 4];
        __half2 h0 = __floats2half2_rn(a.x, a.y);
        __half2 h1 = __floats2half2_rn(a.z, a.w);
        __half2 h2 = __floats2half2_rn(b.x, b.y);
        __half2 h3 = __floats2half2_rn(b.z, b.w);
        uint4 pk;
        pk.x = *(unsigned*)&h0; pk.y = *(unsigned*)&h1;
        pk.z = *(unsigned*)&h2; pk.w = *(unsigned*)&h3;
        *(uint4*)((char*)g_xh + (size_t)(n0 + nn) * 128 + seg * 16) = pk;
    }
}

// ---------------- layer-1 aggregation in x-space (warp per dst) --------------
// lane l: head h = l>>2, quarter q = l&3 -> owns x-channels [16q,16q+16) for head h.
// y[n,h,:] = (1/s_h) * sum_e p_e[h] * x[src_e,:]   (fp16 out, normalized)
__global__ void k_agg1() {
    const int warp = threadIdx.x >> 5, l = threadIdx.x & 31;
    const int n = blockIdx.x * 8 + warp;
    if (n >= N_NODES) return;
    const int h = l >> 2, q = l & 3;
    const float er = g_er1[n * 8 + h];
    const int start = g_off[n], cnt = g_deg[n];

    float s = 0.f;
    float acc[16];
    #pragma unroll
    for (int i = 0; i < 16; ++i) acc[i] = 0.f;

    int k = 0;
    if (cnt >= 4) {
        int cur[4];
        #pragma unroll
        for (int j = 0; j < 4; ++j) cur[j] = g_csr_src[start + j];
        while (k + 4 <= cnt) {
            float e[4];
            #pragma unroll
            for (int j = 0; j < 4; ++j) e[j] = g_el1[cur[j] * 8 + h];
            uint4 xa[4], xb[4];
            #pragma unroll
            for (int j = 0; j < 4; ++j) {
                const char* base = (const char*)g_xh + (size_t)cur[j] * 128 + q * 32;
                xa[j] = *(const uint4*)base;
                xb[j] = *(const uint4*)(base + 16);
            }
            k += 4;
            const bool more = (k + 4 <= cnt);
            if (more) {
                #pragma unroll
                for (int j = 0; j < 4; ++j) cur[j] = g_csr_src[start + k + j];
            }
            #pragma unroll
            for (int j = 0; j < 4; ++j) {
                float ej = e[j] + er;
                ej = (ej > 0.f) ? ej : NEG * ej;
                float p = __expf(ej);
                s += p;
                const __half2* pa = (const __half2*)&xa[j];
                const __half2* pb = (const __half2*)&xb[j];
                #pragma unroll
                for (int u = 0; u < 4; ++u) {
                    float2 fa = __half22float2(pa[u]);
                    float2 fb = __half22float2(pb[u]);
                    acc[2*u + 0] = fmaf(p, fa.x, acc[2*u + 0]);
                    acc[2*u + 1] = fmaf(p, fa.y, acc[2*u + 1]);
                    acc[2*u + 8] = fmaf(p, fb.x, acc[2*u + 8]);
                    acc[2*u + 9] = fmaf(p, fb.y, acc[2*u + 9]);
                }
            }
        }
    }
    for (; k < cnt; ++k) {
        int sn = g_csr_src[start + k];
        float e = g_el1[sn * 8 + h] + er;
        e = (e > 0.f) ? e : NEG * e;
        float p = __expf(e);
        s += p;
        const char* base = (const char*)g_xh + (size_t)sn * 128 + q * 32;
        uint4 xa = *(const uint4*)base;
        uint4 xb = *(const uint4*)(base + 16);
        const __half2* pa = (const __half2*)&xa;
        const __half2* pb = (const __half2*)&xb;
        #pragma unroll
        for (int u = 0; u < 4; ++u) {
            float2 fa = __half22float2(pa[u]);
            float2 fb = __half22float2(pb[u]);
            acc[2*u + 0] = fmaf(p, fa.x, acc[2*u + 0]);
            acc[2*u + 1] = fmaf(p, fa.y, acc[2*u + 1]);
            acc[2*u + 8] = fmaf(p, fb.x, acc[2*u + 8]);
            acc[2*u + 9] = fmaf(p, fb.y, acc[2*u + 9]);
        }
    }

    // normalize + store fp16: 32 B at y[n][h][16q..16q+16)
    float inv = (cnt > 0) ? 1.f / s : 0.f;
    __half2 hv[8];
    #pragma unroll
    for (int u = 0; u < 8; ++u)
        hv[u] = __floats2half2_rn(acc[2*u] * inv, acc[2*u + 1] * inv);
    uint4 p0, p1;
    p0.x = *(unsigned*)&hv[0]; p0.y = *(unsigned*)&hv[1];
    p0.z = *(unsigned*)&hv[2]; p0.w = *(unsigned*)&hv[3];
    p1.x = *(unsigned*)&hv[4]; p1.y = *(unsigned*)&hv[5];
    p1.z = *(unsigned*)&hv[6]; p1.w = *(unsigned*)&hv[7];
    char* base = (char*)g_y + (size_t)n * 1024 + h * 128 + q * 32;
    *(uint4*)base = p0;
    *(uint4*)(base + 16) = p1;
}

// ---------------- gemm2: out = y @ W, + b1, relu, dot W2 -> feat2 ------------
// 256 threads (thread c = head c>>5, o c&31), 32 nodes/block, W column in regs.
__global__ void k_gemm2(const float* __restrict__ W, const float* __restrict__ b1,
                        const float* __restrict__ W2) {
    __shared__ __half ys[32][8][72];      // pad 72: 16B-aligned h-rows, conflict-free
    __shared__ float part[8][32];
    const int tid = threadIdx.x;
    const int n0 = blockIdx.x * 32;
    // load 32 y rows (2048 uint4, 8 per thread)
    #pragma unroll
    for (int j = 0; j < 8; ++j) {
        int flat = tid + 256 * j;          // (n, h, u)
        int n = flat >> 6, rem = flat & 63;
        int h = rem >> 3, u = rem & 7;
        uint4 v = *(const uint4*)((const char*)g_y + (size_t)(n0 + n) * 1024 + h * 128 + u * 16);
        *(uint4*)((char*)&ys[n][h][0] + u * 16) = v;
    }
    const int c = tid, h = c >> 5, o = c & 31;
    float wreg[IN_F];
    #pragma unroll
    for (int i = 0; i < IN_F; ++i) wreg[i] = W[i * CH + c];
    const float b1c = b1[c], w2c = W2[c];
    __syncthreads();

    #pragma unroll 4
    for (int n = 0; n < 32; ++n) {
        const __half2* yr = (const __half2*)&ys[n][h][0];
        float a = 0.f;
        #pragma unroll
        for (int i2 = 0; i2 < 32; ++i2) {
            float2 f = __half22float2(yr[i2]);
            a = fmaf(f.x, wreg[2*i2], a);
            a = fmaf(f.y, wreg[2*i2 + 1], a);
        }
        float v = fmaxf(a + b1c, 0.f) * w2c;
        #pragma unroll
        for (int d = 16; d; d >>= 1) v += __shfl_down_sync(0xffffffffu, v, d);
        if (o == 0) part[h][n] = v;
    }
    __syncthreads();
    // final: 8 partials per node -> feat2
    {
        int n = tid >> 3, w = tid & 7;
        float v = part[w][n];
        #pragma unroll
        for (int d = 4; d; d >>= 1) v += __shfl_down_sync(0xffffffffu, v, d, 8);
        int node = n0 + n;
        if (w == 0 && node < N_NODES) g_feat2[node] = v;
    }
}

// ---------------- layer-2: warp per dst, lanes = edges -----------------------
__global__ void k_gat2(const float* __restrict__ al2p, const float* __restrict__ ar2p,
                       const float* __restrict__ b2p, float* __restrict__ out) {
    const int warp = threadIdx.x >> 5, l = threadIdx.x & 31;
    const int n = blockIdx.x * 8 + warp;
    if (n >= N_NODES) return;
    const float al2 = al2p[0], ar2 = ar2p[0], b2 = b2p[0];
    const float er = g_feat2[n] * ar2;
    const int start = g_off[n], cnt = g_deg[n];
    float s = 0.f, a = 0.f;
    for (int k = l; k < cnt; k += 32) {
        int idx = g_csr_src[start + k];
        float f = g_feat2[idx];
        float e = f * al2 + er;
        e = (e > 0.f) ? e : NEG * e;
        float p = __expf(e);
        s += p;
        a = fmaf(p, f, a);
    }
    #pragma unroll
    for (int d = 16; d; d >>= 1) {
        s += __shfl_down_sync(0xffffffffu, s, d);
        a += __shfl_down_sync(0xffffffffu, a, d);
    }
    if (l == 0) {
        float r = (cnt > 0) ? (a / s + b2) : b2;
        out[n] = 1.f / (1.f + __expf(-r));
    }
}

// ---------------- launch ----------------
extern "C" void kernel_launch(void* const* d_in, const int* in_sizes, int n_in,
                              void* d_out, int out_size) {
    const float* x    = (const float*)d_in[0];
    const int*   src  = (const int*)  d_in[1];
    const int*   dst  = (const int*)  d_in[2];
    const float* W1   = (const float*)d_in[4];
    const float* al1  = (const float*)d_in[5];
    const float* ar1  = (const float*)d_in[6];
    const float* b1   = (const float*)d_in[7];
    const float* W2   = (const float*)d_in[8];
    const float* al2  = (const float*)d_in[9];
    const float* ar2  = (const float*)d_in[10];
    const float* b2   = (const float*)d_in[11];
    float* out = (float*)d_out;

    (void)in_sizes; (void)n_in; (void)out_size;

    k_zero_deg<<<(N_NODES + 255) / 256, 256>>>();
    k_count<<<(N_EDGES / 4 + 255) / 256, 256>>>(dst);
    k_scan<<<1, 1024>>>();
    k_fill<<<(N_EDGES / 4 + 255) / 256, 256>>>(src, dst);

    k_prep<<<(N_NODES + 31) / 32, 256>>>(x, W1, al1, ar1);
    k_agg1<<<(N_NODES + 7) / 8, 256>>>();
    k_gemm2<<<(N_NODES + 31) / 32, 256>>>(W1, b1, W2);

    k_gat2<<<(N_NODES + 7) / 8, 256>>>(al2, ar2, b2, out);
}

// round 10
// speedup vs baseline: 1.1419x; 1.1419x over previous
#include <cuda_runtime.h>
#include <cuda_fp16.h>
#include <math.h>

// Problem constants (fixed by the reference)
#define N_NODES 50000
#define N_EDGES 800000
#define IN_F    64
#define HEADS   8
#define HID     32
#define CH      256          // HEADS*HID
#define NEG     0.2f

// ---------------- scratch (no cudaMalloc allowed) ----------------
__device__ __align__(16) __half g_feat1h[(size_t)N_NODES * CH];  // 25.6 MB fp16 gather table
__device__ float g_el1[N_NODES * HEADS];
__device__ float g_er1[N_NODES * HEADS];
__device__ float g_feat2[N_NODES];
__device__ int   g_deg[N_NODES];
__device__ int   g_off[N_NODES];
__device__ int   g_rank[N_EDGES];
__device__ int   g_csr_src[N_EDGES];

// ---------------- CSR construction ----------------
__global__ void k_zero_deg() {
    int i = blockIdx.x * blockDim.x + threadIdx.x;
    if (i < N_NODES) g_deg[i] = 0;
}

// count degrees AND record each edge's rank within its dst segment
__global__ void k_count(const int* __restrict__ dst) {
    int i = (blockIdx.x * blockDim.x + threadIdx.x) * 4;
    if (i + 3 < N_EDGES) {
        int4 d = *(const int4*)(dst + i);
        int4 r;
        r.x = atomicAdd(&g_deg[d.x], 1);
        r.y = atomicAdd(&g_deg[d.y], 1);
        r.z = atomicAdd(&g_deg[d.z], 1);
        r.w = atomicAdd(&g_deg[d.w], 1);
        *(int4*)(g_rank + i) = r;
    } else {
        for (int e = i; e < N_EDGES; ++e)
            g_rank[e] = atomicAdd(&g_deg[dst[e]], 1);
    }
}

// single-block exclusive scan over 50000 degrees -> offsets
__global__ void k_scan() {
    __shared__ int sums[1024];
    const int t = threadIdx.x;
    const int chunk = (N_NODES + 1023) / 1024;
    int begin = t * chunk;
    int end   = begin + chunk; if (end > N_NODES) end = N_NODES;
    int s = 0;
    for (int i = begin; i < end; ++i) s += g_deg[i];
    sums[t] = s;
    __syncthreads();
    for (int ofs = 1; ofs < 1024; ofs <<= 1) {
        int v = (t >= ofs) ? sums[t - ofs] : 0;
        __syncthreads();
        sums[t] += v;
        __syncthreads();
    }
    int run = (t == 0) ? 0 : sums[t - 1];
    for (int i = begin; i < end; ++i) {
        g_off[i] = run;
        run += g_deg[i];
    }
}

// non-atomic fill: slot = off[dst] + rank[e] is unique per edge
__global__ void k_fill(const int* __restrict__ src, const int* __restrict__ dst) {
    int i = (blockIdx.x * blockDim.x + threadIdx.x) * 4;
    if (i + 3 < N_EDGES) {
        int4 d = *(const int4*)(dst + i);
        int4 s = *(const int4*)(src + i);
        int4 r = *(const int4*)(g_rank + i);
        g_csr_src[g_off[d.x] + r.x] = s.x;
        g_csr_src[g_off[d.y] + r.y] = s.y;
        g_csr_src[g_off[d.z] + r.z] = s.z;
        g_csr_src[g_off[d.w] + r.w] = s.w;
    } else {
        for (int e = i; e < N_EDGES; ++e)
            g_csr_src[g_off[dst[e]] + g_rank[e]] = src[e];
    }
}

// ---------------- layer-1 GEMM + el/er (in-block Al/Ar projection) -----------
// 256 threads (one output channel each), 32 nodes per block.
// LDS.128 x reads, W column in registers; el/er via x . (W.al) dots.
__global__ void k_gemm(const float* __restrict__ x, const float* __restrict__ W,
                       const float* __restrict__ al, const float* __restrict__ ar) {
    __shared__ float xs[32][IN_F + 4];
    __shared__ float sAl[IN_F][9], sAr[IN_F][9];
    const int tid = threadIdx.x;
    const int n0 = blockIdx.x * 32;
    // load x rows as float4 (512 float4 per block, 2 per thread)
    #pragma unroll
    for (int r = 0; r < 2; ++r) {
        int e = tid + r * 256;             // node = e>>4, i4 = e&15
        int n = e >> 4, i4 = e & 15;
        int node = n0 + n;
        float4 v = (node < N_NODES) ? ((const float4*)(x + (size_t)node * IN_F))[i4]
                                    : make_float4(0.f, 0.f, 0.f, 0.f);
        *(float4*)&xs[n][i4 * 4] = v;
    }
    // in-block projection Al = W.al, Ar = W.ar (2 entries per thread, 32-FMA dots)
    #pragma unroll
    for (int r = 0; r < 2; ++r) {
        int e = tid + r * 256;
        int i = e >> 3, h = e & 7;
        float sl = 0.f, sr = 0.f;
        #pragma unroll 8
        for (int o = 0; o < HID; ++o) {
            float w = W[i * CH + h * HID + o];
            sl = fmaf(w, al[h * HID + o], sl);
            sr = fmaf(w, ar[h * HID + o], sr);
        }
        sAl[i][h] = sl;
        sAr[i][h] = sr;
    }
    __syncthreads();

    const int c = tid;
    float wreg[IN_F];
    #pragma unroll
    for (int i = 0; i < IN_F; ++i) wreg[i] = W[i * CH + c];

    #pragma unroll 4
    for (int n = 0; n < 32; ++n) {
        const float4* xr = (const float4*)xs[n];
        float a = 0.f;
        #pragma unroll
        for (int i4 = 0; i4 < 16; ++i4) {
            float4 xv = xr[i4];
            a = fmaf(xv.x, wreg[4 * i4 + 0], a);
            a = fmaf(xv.y, wreg[4 * i4 + 1], a);
            a = fmaf(xv.z, wreg[4 * i4 + 2], a);
            a = fmaf(xv.w, wreg[4 * i4 + 3], a);
        }
        int node = n0 + n;
        if (node < N_NODES) g_feat1h[(size_t)node * CH + c] = __float2half_rn(a);
    }

    // el/er: thread t handles (node tid>>3, head tid&7): two 64-wide dots
    const int nn = tid >> 3, h = tid & 7;
    const float4* xr = (const float4*)xs[nn];
    float sl = 0.f, sr = 0.f;
    #pragma unroll
    for (int i4 = 0; i4 < 16; ++i4) {
        float4 xv = xr[i4];
        sl = fmaf(xv.x, sAl[4*i4+0][h], sl); sr = fmaf(xv.x, sAr[4*i4+0][h], sr);
        sl = fmaf(xv.y, sAl[4*i4+1][h], sl); sr = fmaf(xv.y, sAr[4*i4+1][h], sr);
        sl = fmaf(xv.z, sAl[4*i4+2][h], sl); sr = fmaf(xv.z, sAr[4*i4+2][h], sr);
        sl = fmaf(xv.w, sAl[4*i4+3][h], sl); sr = fmaf(xv.w, sAr[4*i4+3][h], sr);
    }
    int node = n0 + nn;
    if (node < N_NODES) {
        g_el1[node * 8 + h] = sl;
        g_er1[node * 8 + h] = sr;
    }
}

// ---------------- layer-1 aggregation (warp per dst, batch-8 + prefetch) -----
// Single-pass softmax (no max-shift: logits bounded far below exp overflow).
// lane l owns channels [l*8, l*8+8); head = l/4.
// epilogue fuses +b1, ReLU, layer-2 linear h.W2 -> g_feat2[n]
__global__ void k_agg1(const float* __restrict__ b1, const float* __restrict__ W2) {
    const int warp = threadIdx.x >> 5, l = threadIdx.x & 31;
    const int n = blockIdx.x * 8 + warp;
    if (n >= N_NODES) return;
    const int h = l >> 2;
    const float er = g_er1[n * 8 + h];
    const int start = g_off[n], cnt = g_deg[n];

    float s = 0.f;
    float acc[8];
    #pragma unroll
    for (int i = 0; i < 8; ++i) acc[i] = 0.f;

    const int co = l << 3;
    int k = 0;
    if (cnt >= 8) {
        int cur[8];
        #pragma unroll
        for (int j = 0; j < 8; ++j) cur[j] = g_csr_src[start + j];
        while (k + 8 <= cnt) {
            float e[8];
            #pragma unroll
            for (int j = 0; j < 8; ++j) e[j] = g_el1[cur[j] * 8 + h];
            uint4 r[8];
            #pragma unroll
            for (int j = 0; j < 8; ++j)
                r[j] = *reinterpret_cast<const uint4*>(g_feat1h + (size_t)cur[j] * CH + co);
            k += 8;
            const bool more = (k + 8 <= cnt);
            if (more) {
                #pragma unroll
                for (int j = 0; j < 8; ++j) cur[j] = g_csr_src[start + k + j];
            }
            float p[8];
            #pragma unroll
            for (int j = 0; j < 8; ++j) {
                float ej = e[j] + er;
                ej = (ej > 0.f) ? ej : NEG * ej;
                p[j] = __expf(ej);
            }
            #pragma unroll
            for (int j = 0; j < 8; ++j) s += p[j];
            #pragma unroll
            for (int j = 0; j < 8; ++j) {
                float2 f0 = __half22float2(*reinterpret_cast<__half2*>(&r[j].x));
                float2 f1 = __half22float2(*reinterpret_cast<__half2*>(&r[j].y));
                float2 f2 = __half22float2(*reinterpret_cast<__half2*>(&r[j].z));
                float2 f3 = __half22float2(*reinterpret_cast<__half2*>(&r[j].w));
                acc[0] = fmaf(p[j], f0.x, acc[0]);
                acc[1] = fmaf(p[j], f0.y, acc[1]);
                acc[2] = fmaf(p[j], f1.x, acc[2]);
                acc[3] = fmaf(p[j], f1.y, acc[3]);
                acc[4] = fmaf(p[j], f2.x, acc[4]);
                acc[5] = fmaf(p[j], f2.y, acc[5]);
                acc[6] = fmaf(p[j], f3.x, acc[6]);
                acc[7] = fmaf(p[j], f3.y, acc[7]);
            }
        }
    }
    for (; k < cnt; ++k) {
        int sn = g_csr_src[start + k];
        float e = g_el1[sn * 8 + h] + er;
        e = (e > 0.f) ? e : NEG * e;
        float p = __expf(e);
        s += p;
        uint4 rr = *reinterpret_cast<const uint4*>(g_feat1h + (size_t)sn * CH + co);
        float2 f0 = __half22float2(*reinterpret_cast<__half2*>(&rr.x));
        float2 f1 = __half22float2(*reinterpret_cast<__half2*>(&rr.y));
        float2 f2 = __half22float2(*reinterpret_cast<__half2*>(&rr.z));
        float2 f3 = __half22float2(*reinterpret_cast<__half2*>(&rr.w));
        acc[0] = fmaf(p, f0.x, acc[0]);
        acc[1] = fmaf(p, f0.y, acc[1]);
        acc[2] = fmaf(p, f1.x, acc[2]);
        acc[3] = fmaf(p, f1.y, acc[3]);
        acc[4] = fmaf(p, f2.x, acc[4]);
        acc[5] = fmaf(p, f2.y, acc[5]);
        acc[6] = fmaf(p, f3.x, acc[6]);
        acc[7] = fmaf(p, f3.y, acc[7]);
    }

    float4 bv0 = *reinterpret_cast<const float4*>(b1 + co);
    float4 bv1 = *reinterpret_cast<const float4*>(b1 + co + 4);
    float4 wv0 = *reinterpret_cast<const float4*>(W2 + co);
    float4 wv1 = *reinterpret_cast<const float4*>(W2 + co + 4);
    const float bb[8] = {bv0.x, bv0.y, bv0.z, bv0.w, bv1.x, bv1.y, bv1.z, bv1.w};
    const float ww[8] = {wv0.x, wv0.y, wv0.z, wv0.w, wv1.x, wv1.y, wv1.z, wv1.w};
    float inv = (cnt > 0) ? 1.f / s : 0.f;
    float dot = 0.f;
    #pragma unroll
    for (int i = 0; i < 8; ++i) {
        float v = acc[i] * inv + bb[i];
        v = fmaxf(v, 0.f);
        dot = fmaf(v, ww[i], dot);
    }
    #pragma unroll
    for (int o = 16; o; o >>= 1) dot += __shfl_xor_sync(0xffffffffu, dot, o);
    if (l == 0) g_feat2[n] = dot;
}

// ---------------- layer-2: warp per dst, lanes = edges -----------------------
__global__ void k_gat2(const float* __restrict__ al2p, const float* __restrict__ ar2p,
                       const float* __restrict__ b2p, float* __restrict__ out) {
    const int warp = threadIdx.x >> 5, l = threadIdx.x & 31;
    const int n = blockIdx.x * 8 + warp;
    if (n >= N_NODES) return;
    const float al2 = al2p[0], ar2 = ar2p[0], b2 = b2p[0];
    const float er = g_feat2[n] * ar2;
    const int start = g_off[n], cnt = g_deg[n];
    float s = 0.f, a = 0.f;
    for (int k = l; k < cnt; k += 32) {
        int idx = g_csr_src[start + k];
        float f = g_feat2[idx];
        float e = f * al2 + er;
        e = (e > 0.f) ? e : NEG * e;
        float p = __expf(e);
        s += p;
        a = fmaf(p, f, a);
    }
    #pragma unroll
    for (int d = 16; d; d >>= 1) {
        s += __shfl_down_sync(0xffffffffu, s, d);
        a += __shfl_down_sync(0xffffffffu, a, d);
    }
    if (l == 0) {
        float r = (cnt > 0) ? (a / s + b2) : b2;
        out[n] = 1.f / (1.f + __expf(-r));
    }
}

// ---------------- launch (fork/join: CSR build || gemm) ----------------------
extern "C" void kernel_launch(void* const* d_in, const int* in_sizes, int n_in,
                              void* d_out, int out_size) {
    const float* x    = (const float*)d_in[0];   // [N,64]
    const int*   src  = (const int*)  d_in[1];   // [E]
    const int*   dst  = (const int*)  d_in[2];   // [E]
    // d_in[3] edge_types: unused
    const float* W1   = (const float*)d_in[4];   // [64,8,32]
    const float* al1  = (const float*)d_in[5];   // [8,32]
    const float* ar1  = (const float*)d_in[6];   // [8,32]
    const float* b1   = (const float*)d_in[7];   // [8,32]
    const float* W2   = (const float*)d_in[8];   // [256,1,1]
    const float* al2  = (const float*)d_in[9];   // [1,1]
    const float* ar2  = (const float*)d_in[10];  // [1,1]
    const float* b2   = (const float*)d_in[11];  // [1,1]
    float* out = (float*)d_out;                  // [N,1]

    (void)in_sizes; (void)n_in; (void)out_size;

    // side stream + events for fork/join (created once; harness calls
    // kernel_launch only a handful of times, replays use the captured graph)
    static cudaStream_t s2 = nullptr;
    static cudaEvent_t evFork = nullptr, evJoin = nullptr;
    if (s2 == nullptr) {
        cudaStreamCreateWithFlags(&s2, cudaStreamNonBlocking);
        cudaEventCreateWithFlags(&evFork, cudaEventDisableTiming);
        cudaEventCreateWithFlags(&evJoin, cudaEventDisableTiming);
    }

    // fork: gemm (independent of CSR) runs on s2
    cudaEventRecord(evFork, 0);
    cudaStreamWaitEvent(s2, evFork, 0);
    k_gemm<<<(N_NODES + 31) / 32, 256, 0, s2>>>(x, W1, al1, ar1);
    cudaEventRecord(evJoin, s2);

    // CSR build on the main stream (overlaps with gemm)
    k_zero_deg<<<(N_NODES + 255) / 256, 256>>>();
    k_count<<<(N_EDGES / 4 + 255) / 256, 256>>>(dst);
    k_scan<<<1, 1024>>>();
    k_fill<<<(N_EDGES / 4 + 255) / 256, 256>>>(src, dst);

    // join, then aggregation + layer 2
    cudaStreamWaitEvent(0, evJoin, 0);
    k_agg1<<<(N_NODES + 7) / 8, 256>>>(b1, W2);
    k_gat2<<<(N_NODES + 7) / 8, 256>>>(al2, ar2, b2, out);
}

// round 11
// speedup vs baseline: 1.2024x; 1.0529x over previous
#include <cuda_runtime.h>
#include <cuda_fp16.h>
#include <math.h>

// Problem constants (fixed by the reference)
#define N_NODES 50000
#define N_EDGES 800000
#define IN_F    64
#define HEADS   8
#define HID     32
#define CH      256          // HEADS*HID
#define NEG     0.2f

#define SCAN_B  1024
#define NBLK    ((N_NODES + SCAN_B - 1) / SCAN_B)   // 49

// ---------------- scratch (no cudaMalloc allowed) ----------------
__device__ __align__(16) __half g_feat1h[(size_t)N_NODES * CH];  // 25.6 MB fp16 gather table
__device__ float g_el1[N_NODES * HEADS];
__device__ float g_er1[N_NODES * HEADS];
__device__ float g_feat2[N_NODES];
__device__ int   g_deg[N_NODES];
__device__ int   g_off[N_NODES];
__device__ int   g_rank[N_EDGES];
__device__ int   g_csr_src[N_EDGES];
__device__ int   g_bsum[NBLK];
__device__ int   g_boff[NBLK];

// ---------------- CSR construction ----------------
__global__ void k_zero_deg() {
    int i = blockIdx.x * blockDim.x + threadIdx.x;
    if (i < N_NODES) g_deg[i] = 0;
}

// count degrees AND record each edge's rank within its dst segment
__global__ void k_count(const int* __restrict__ dst) {
    int i = (blockIdx.x * blockDim.x + threadIdx.x) * 4;
    if (i + 3 < N_EDGES) {
        int4 d = *(const int4*)(dst + i);
        int4 r;
        r.x = atomicAdd(&g_deg[d.x], 1);
        r.y = atomicAdd(&g_deg[d.y], 1);
        r.z = atomicAdd(&g_deg[d.z], 1);
        r.w = atomicAdd(&g_deg[d.w], 1);
        *(int4*)(g_rank + i) = r;
    } else {
        for (int e = i; e < N_EDGES; ++e)
            g_rank[e] = atomicAdd(&g_deg[dst[e]], 1);
    }
}

// scan stage A: per-block (1024-wide tile) degree sums, coalesced
__global__ void k_scan_a() {
    __shared__ int sh[8];
    const int b = blockIdx.x, t = threadIdx.x;   // 256 threads
    const int base = b * SCAN_B;
    int s = 0;
    #pragma unroll
    for (int j = 0; j < 4; ++j) {
        int i = base + t + j * 256;
        if (i < N_NODES) s += g_deg[i];
    }
    #pragma unroll
    for (int o = 16; o; o >>= 1) s += __shfl_down_sync(0xffffffffu, s, o);
    if ((t & 31) == 0) sh[t >> 5] = s;
    __syncthreads();
    if (t < 8) {
        int v = sh[t];
        #pragma unroll
        for (int o = 4; o; o >>= 1) v += __shfl_down_sync(0xffu, v, o, 8);
        if (t == 0) g_bsum[b] = v;
    }
}

// scan stage B: exclusive scan of the 49 block sums (1 block, 64 threads)
__global__ void k_scan_b() {
    __shared__ int sh[64];
    const int t = threadIdx.x;
    int v = (t < NBLK) ? g_bsum[t] : 0;
    sh[t] = v;
    __syncthreads();
    for (int o = 1; o < 64; o <<= 1) {
        int u = (t >= o) ? sh[t - o] : 0;
        __syncthreads();
        sh[t] += u;
        __syncthreads();
    }
    if (t < NBLK) g_boff[t] = sh[t] - v;   // exclusive
}

// scan stage C: in-block Hillis-Steele + block offset -> g_off
__global__ void k_scan_c() {
    __shared__ int sh[SCAN_B];
    const int b = blockIdx.x, t = threadIdx.x;   // 1024 threads
    const int i = b * SCAN_B + t;
    int v = (i < N_NODES) ? g_deg[i] : 0;
    sh[t] = v;
    __syncthreads();
    for (int o = 1; o < SCAN_B; o <<= 1) {
        int u = (t >= o) ? sh[t - o] : 0;
        __syncthreads();
        sh[t] += u;
        __syncthreads();
    }
    if (i < N_NODES) g_off[i] = g_boff[b] + sh[t] - v;   // exclusive
}

// non-atomic fill: slot = off[dst] + rank[e] is unique per edge
__global__ void k_fill(const int* __restrict__ src, const int* __restrict__ dst) {
    int i = (blockIdx.x * blockDim.x + threadIdx.x) * 4;
    if (i + 3 < N_EDGES) {
        int4 d = *(const int4*)(dst + i);
        int4 s = *(const int4*)(src + i);
        int4 r = *(const int4*)(g_rank + i);
        g_csr_src[g_off[d.x] + r.x] = s.x;
        g_csr_src[g_off[d.y] + r.y] = s.y;
        g_csr_src[g_off[d.z] + r.z] = s.z;
        g_csr_src[g_off[d.w] + r.w] = s.w;
    } else {
        for (int e = i; e < N_EDGES; ++e)
            g_csr_src[g_off[dst[e]] + g_rank[e]] = src[e];
    }
}

// ---------------- layer-1 GEMM + el/er (in-block Al/Ar projection) -----------
// 256 threads (one output channel each), 32 nodes per block.
__global__ void k_gemm(const float* __restrict__ x, const float* __restrict__ W,
                       const float* __restrict__ al, const float* __restrict__ ar) {
    __shared__ float xs[32][IN_F + 4];
    __shared__ float sAl[IN_F][9], sAr[IN_F][9];
    const int tid = threadIdx.x;
    const int n0 = blockIdx.x * 32;
    #pragma unroll
    for (int r = 0; r < 2; ++r) {
        int e = tid + r * 256;
        int n = e >> 4, i4 = e & 15;
        int node = n0 + n;
        float4 v = (node < N_NODES) ? ((const float4*)(x + (size_t)node * IN_F))[i4]
                                    : make_float4(0.f, 0.f, 0.f, 0.f);
        *(float4*)&xs[n][i4 * 4] = v;
    }
    #pragma unroll
    for (int r = 0; r < 2; ++r) {
        int e = tid + r * 256;
        int i = e >> 3, h = e & 7;
        float sl = 0.f, sr = 0.f;
        #pragma unroll 8
        for (int o = 0; o < HID; ++o) {
            float w = W[i * CH + h * HID + o];
            sl = fmaf(w, al[h * HID + o], sl);
            sr = fmaf(w, ar[h * HID + o], sr);
        }
        sAl[i][h] = sl;
        sAr[i][h] = sr;
    }
    __syncthreads();

    const int c = tid;
    float wreg[IN_F];
    #pragma unroll
    for (int i = 0; i < IN_F; ++i) wreg[i] = W[i * CH + c];

    #pragma unroll 4
    for (int n = 0; n < 32; ++n) {
        const float4* xr = (const float4*)xs[n];
        float a = 0.f;
        #pragma unroll
        for (int i4 = 0; i4 < 16; ++i4) {
            float4 xv = xr[i4];
            a = fmaf(xv.x, wreg[4 * i4 + 0], a);
            a = fmaf(xv.y, wreg[4 * i4 + 1], a);
            a = fmaf(xv.z, wreg[4 * i4 + 2], a);
            a = fmaf(xv.w, wreg[4 * i4 + 3], a);
        }
        int node = n0 + n;
        if (node < N_NODES) g_feat1h[(size_t)node * CH + c] = __float2half_rn(a);
    }

    const int nn = tid >> 3, h = tid & 7;
    const float4* xr = (const float4*)xs[nn];
    float sl = 0.f, sr = 0.f;
    #pragma unroll
    for (int i4 = 0; i4 < 16; ++i4) {
        float4 xv = xr[i4];
        sl = fmaf(xv.x, sAl[4*i4+0][h], sl); sr = fmaf(xv.x, sAr[4*i4+0][h], sr);
        sl = fmaf(xv.y, sAl[4*i4+1][h], sl); sr = fmaf(xv.y, sAr[4*i4+1][h], sr);
        sl = fmaf(xv.z, sAl[4*i4+2][h], sl); sr = fmaf(xv.z, sAr[4*i4+2][h], sr);
        sl = fmaf(xv.w, sAl[4*i4+3][h], sl); sr = fmaf(xv.w, sAr[4*i4+3][h], sr);
    }
    int node = n0 + nn;
    if (node < N_NODES) {
        g_el1[node * 8 + h] = sl;
        g_er1[node * 8 + h] = sr;
    }
}

// ---------------- layer-1 aggregation (warp per dst, batch-8 + prefetch) -----
__global__ void k_agg1(const float* __restrict__ b1, const float* __restrict__ W2) {
    const int warp = threadIdx.x >> 5, l = threadIdx.x & 31;
    const int n = blockIdx.x * 8 + warp;
    if (n >= N_NODES) return;
    const int h = l >> 2;
    const float er = g_er1[n * 8 + h];
    const int start = g_off[n], cnt = g_deg[n];

    float s = 0.f;
    float acc[8];
    #pragma unroll
    for (int i = 0; i < 8; ++i) acc[i] = 0.f;

    const int co = l << 3;
    int k = 0;
    if (cnt >= 8) {
        int cur[8];
        #pragma unroll
        for (int j = 0; j < 8; ++j) cur[j] = g_csr_src[start + j];
        while (k + 8 <= cnt) {
            float e[8];
            #pragma unroll
            for (int j = 0; j < 8; ++j) e[j] = g_el1[cur[j] * 8 + h];
            uint4 r[8];
            #pragma unroll
            for (int j = 0; j < 8; ++j)
                r[j] = *reinterpret_cast<const uint4*>(g_feat1h + (size_t)cur[j] * CH + co);
            k += 8;
            const bool more = (k + 8 <= cnt);
            if (more) {
                #pragma unroll
                for (int j = 0; j < 8; ++j) cur[j] = g_csr_src[start + k + j];
            }
            float p[8];
            #pragma unroll
            for (int j = 0; j < 8; ++j) {
                float ej = e[j] + er;
                ej = (ej > 0.f) ? ej : NEG * ej;
                p[j] = __expf(ej);
            }
            #pragma unroll
            for (int j = 0; j < 8; ++j) s += p[j];
            #pragma unroll
            for (int j = 0; j < 8; ++j) {
                float2 f0 = __half22float2(*reinterpret_cast<__half2*>(&r[j].x));
                float2 f1 = __half22float2(*reinterpret_cast<__half2*>(&r[j].y));
                float2 f2 = __half22float2(*reinterpret_cast<__half2*>(&r[j].z));
                float2 f3 = __half22float2(*reinterpret_cast<__half2*>(&r[j].w));
                acc[0] = fmaf(p[j], f0.x, acc[0]);
                acc[1] = fmaf(p[j], f0.y, acc[1]);
                acc[2] = fmaf(p[j], f1.x, acc[2]);
                acc[3] = fmaf(p[j], f1.y, acc[3]);
                acc[4] = fmaf(p[j], f2.x, acc[4]);
                acc[5] = fmaf(p[j], f2.y, acc[5]);
                acc[6] = fmaf(p[j], f3.x, acc[6]);
                acc[7] = fmaf(p[j], f3.y, acc[7]);
            }
        }
    }
    for (; k < cnt; ++k) {
        int sn = g_csr_src[start + k];
        float e = g_el1[sn * 8 + h] + er;
        e = (e > 0.f) ? e : NEG * e;
        float p = __expf(e);
        s += p;
        uint4 rr = *reinterpret_cast<const uint4*>(g_feat1h + (size_t)sn * CH + co);
        float2 f0 = __half22float2(*reinterpret_cast<__half2*>(&rr.x));
        float2 f1 = __half22float2(*reinterpret_cast<__half2*>(&rr.y));
        float2 f2 = __half22float2(*reinterpret_cast<__half2*>(&rr.z));
        float2 f3 = __half22float2(*reinterpret_cast<__half2*>(&rr.w));
        acc[0] = fmaf(p, f0.x, acc[0]);
        acc[1] = fmaf(p, f0.y, acc[1]);
        acc[2] = fmaf(p, f1.x, acc[2]);
        acc[3] = fmaf(p, f1.y, acc[3]);
        acc[4] = fmaf(p, f2.x, acc[4]);
        acc[5] = fmaf(p, f2.y, acc[5]);
        acc[6] = fmaf(p, f3.x, acc[6]);
        acc[7] = fmaf(p, f3.y, acc[7]);
    }

    float4 bv0 = *reinterpret_cast<const float4*>(b1 + co);
    float4 bv1 = *reinterpret_cast<const float4*>(b1 + co + 4);
    float4 wv0 = *reinterpret_cast<const float4*>(W2 + co);
    float4 wv1 = *reinterpret_cast<const float4*>(W2 + co + 4);
    const float bb[8] = {bv0.x, bv0.y, bv0.z, bv0.w, bv1.x, bv1.y, bv1.z, bv1.w};
    const float ww[8] = {wv0.x, wv0.y, wv0.z, wv0.w, wv1.x, wv1.y, wv1.z, wv1.w};
    float inv = (cnt > 0) ? 1.f / s : 0.f;
    float dot = 0.f;
    #pragma unroll
    for (int i = 0; i < 8; ++i) {
        float v = acc[i] * inv + bb[i];
        v = fmaxf(v, 0.f);
        dot = fmaf(v, ww[i], dot);
    }
    #pragma unroll
    for (int o = 16; o; o >>= 1) dot += __shfl_xor_sync(0xffffffffu, dot, o);
    if (l == 0) g_feat2[n] = dot;
}

// ---------------- layer-2: warp per dst, lanes = edges -----------------------
__global__ void k_gat2(const float* __restrict__ al2p, const float* __restrict__ ar2p,
                       const float* __restrict__ b2p, float* __restrict__ out) {
    const int warp = threadIdx.x >> 5, l = threadIdx.x & 31;
    const int n = blockIdx.x * 8 + warp;
    if (n >= N_NODES) return;
    const float al2 = al2p[0], ar2 = ar2p[0], b2 = b2p[0];
    const float er = g_feat2[n] * ar2;
    const int start = g_off[n], cnt = g_deg[n];
    float s = 0.f, a = 0.f;
    for (int k = l; k < cnt; k += 32) {
        int idx = g_csr_src[start + k];
        float f = g_feat2[idx];
        float e = f * al2 + er;
        e = (e > 0.f) ? e : NEG * e;
        float p = __expf(e);
        s += p;
        a = fmaf(p, f, a);
    }
    #pragma unroll
    for (int d = 16; d; d >>= 1) {
        s += __shfl_down_sync(0xffffffffu, s, d);
        a += __shfl_down_sync(0xffffffffu, a, d);
    }
    if (l == 0) {
        float r = (cnt > 0) ? (a / s + b2) : b2;
        out[n] = 1.f / (1.f + __expf(-r));
    }
}

// ---------------- launch (serial, single stream) -----------------------------
extern "C" void kernel_launch(void* const* d_in, const int* in_sizes, int n_in,
                              void* d_out, int out_size) {
    const float* x    = (const float*)d_in[0];   // [N,64]
    const int*   src  = (const int*)  d_in[1];   // [E]
    const int*   dst  = (const int*)  d_in[2];   // [E]
    // d_in[3] edge_types: unused
    const float* W1   = (const float*)d_in[4];   // [64,8,32]
    const float* al1  = (const float*)d_in[5];   // [8,32]
    const float* ar1  = (const float*)d_in[6];   // [8,32]
    const float* b1   = (const float*)d_in[7];   // [8,32]
    const float* W2   = (const float*)d_in[8];   // [256,1,1]
    const float* al2  = (const float*)d_in[9];   // [1,1]
    const float* ar2  = (const float*)d_in[10];  // [1,1]
    const float* b2   = (const float*)d_in[11];  // [1,1]
    float* out = (float*)d_out;                  // [N,1]

    (void)in_sizes; (void)n_in; (void)out_size;

    // CSR build (parallel scan)
    k_zero_deg<<<(N_NODES + 255) / 256, 256>>>();
    k_count<<<(N_EDGES / 4 + 255) / 256, 256>>>(dst);
    k_scan_a<<<NBLK, 256>>>();
    k_scan_b<<<1, 64>>>();
    k_scan_c<<<NBLK, SCAN_B>>>();
    k_fill<<<(N_EDGES / 4 + 255) / 256, 256>>>(src, dst);

    // layer 1
    k_gemm<<<(N_NODES + 31) / 32, 256>>>(x, W1, al1, ar1);
    k_agg1<<<(N_NODES + 7) / 8, 256>>>(b1, W2);

    // layer 2
    k_gat2<<<(N_NODES + 7) / 8, 256>>>(al2, ar2, b2, out);
}

// round 14
// speedup vs baseline: 2.2175x; 1.8443x over previous
#include <cuda_runtime.h>
#include <cuda_fp16.h>
#include <math.h>

// Problem constants (fixed by the reference)
#define N_NODES 50000
#define N_EDGES 800000
#define IN_F    64
#define HEADS   8
#define HID     32
#define CH      256          // HEADS*HID
#define NEG     0.2f

#define SCAN_B  1024
#define NBLK    ((N_NODES + SCAN_B - 1) / SCAN_B)   // 49

// ---------------- scratch (no cudaMalloc allowed) ----------------
__device__ __align__(16) __half g_feat1h[(size_t)N_NODES * CH];  // 25.6 MB fp16 gather table
__device__ float g_el1[N_NODES * HEADS];
__device__ float g_er1[N_NODES * HEADS];
__device__ float g_feat2[N_NODES];
__device__ int   g_deg[N_NODES];
__device__ int   g_off[N_NODES];
__device__ int   g_rank[N_EDGES];
__device__ int   g_csr_src[N_EDGES];
__device__ float g_Al[IN_F * HEADS];
__device__ float g_Ar[IN_F * HEADS];
__device__ int   g_bsum[NBLK];
__device__ int   g_boff[NBLK];

// ---------------- CSR construction ----------------
__global__ void k_zero_deg() {
    int i = blockIdx.x * blockDim.x + threadIdx.x;
    if (i < N_NODES) g_deg[i] = 0;
}

// count degrees AND record each edge's rank within its dst segment
__global__ void k_count(const int* __restrict__ dst) {
    int i = (blockIdx.x * blockDim.x + threadIdx.x) * 4;
    if (i + 3 < N_EDGES) {
        int4 d = *(const int4*)(dst + i);
        int4 r;
        r.x = atomicAdd(&g_deg[d.x], 1);
        r.y = atomicAdd(&g_deg[d.y], 1);
        r.z = atomicAdd(&g_deg[d.z], 1);
        r.w = atomicAdd(&g_deg[d.w], 1);
        *(int4*)(g_rank + i) = r;
    } else {
        for (int e = i; e < N_EDGES; ++e)
            g_rank[e] = atomicAdd(&g_deg[dst[e]], 1);
    }
}

// scan stage A: per-1024-tile degree sums (49 blocks x 256 threads, coalesced)
__global__ void k_scan_a() {
    __shared__ int sh[8];
    const int b = blockIdx.x, t = threadIdx.x;
    const int base = b * SCAN_B;
    int s = 0;
    #pragma unroll
    for (int j = 0; j < 4; ++j) {
        int i = base + t + j * 256;
        if (i < N_NODES) s += g_deg[i];
    }
    #pragma unroll
    for (int o = 16; o; o >>= 1) s += __shfl_down_sync(0xffffffffu, s, o);
    if ((t & 31) == 0) sh[t >> 5] = s;
    __syncthreads();
    if (t < 8) {
        int v = sh[t];
        #pragma unroll
        for (int o = 4; o; o >>= 1) v += __shfl_down_sync(0xffu, v, o, 8);
        if (t == 0) g_bsum[b] = v;
    }
}

// scan stage B: exclusive scan of 49 block sums (1 block, 64 threads)
__global__ void k_scan_b() {
    __shared__ int sh[64];
    const int t = threadIdx.x;
    int v = (t < NBLK) ? g_bsum[t] : 0;
    sh[t] = v;
    __syncthreads();
    for (int o = 1; o < 64; o <<= 1) {
        int u = (t >= o) ? sh[t - o] : 0;
        __syncthreads();
        sh[t] += u;
        __syncthreads();
    }
    if (t < NBLK) g_boff[t] = sh[t] - v;   // exclusive
}

// scan stage C: in-block Hillis-Steele + block offset -> g_off
__global__ void k_scan_c() {
    __shared__ int sh[SCAN_B];
    const int b = blockIdx.x, t = threadIdx.x;   // 1024 threads
    const int i = b * SCAN_B + t;
    int v = (i < N_NODES) ? g_deg[i] : 0;
    sh[t] = v;
    __syncthreads();
    for (int o = 1; o < SCAN_B; o <<= 1) {
        int u = (t >= o) ? sh[t - o] : 0;
        __syncthreads();
        sh[t] += u;
        __syncthreads();
    }
    if (i < N_NODES) g_off[i] = g_boff[b] + sh[t] - v;   // exclusive
}

// non-atomic fill: slot = off[dst] + rank[e] is unique per edge
__global__ void k_fill(const int* __restrict__ src, const int* __restrict__ dst) {
    int i = (blockIdx.x * blockDim.x + threadIdx.x) * 4;
    if (i + 3 < N_EDGES) {
        int4 d = *(const int4*)(dst + i);
        int4 s = *(const int4*)(src + i);
        int4 r = *(const int4*)(g_rank + i);
        g_csr_src[g_off[d.x] + r.x] = s.x;
        g_csr_src[g_off[d.y] + r.y] = s.y;
        g_csr_src[g_off[d.z] + r.z] = s.z;
        g_csr_src[g_off[d.w] + r.w] = s.w;
    } else {
        for (int e = i; e < N_EDGES; ++e)
            g_csr_src[g_off[dst[e]] + g_rank[e]] = src[e];
    }
}

// ---------------- tiny projection: Al = W . al, Ar = W . ar ------------------
__global__ void k_proj(const float* __restrict__ W, const float* __restrict__ al,
                       const float* __restrict__ ar) {
    int t = threadIdx.x;            // 512 threads
    int i = t >> 3, h = t & 7;
    float sl = 0.f, sr = 0.f;
    #pragma unroll 8
    for (int o = 0; o < HID; ++o) {
        float w = W[i * CH + h * HID + o];
        sl = fmaf(w, al[h * HID + o], sl);
        sr = fmaf(w, ar[h * HID + o], sr);
    }
    g_Al[i * 8 + h] = sl;
    g_Ar[i * 8 + h] = sr;
}

// ---------------- layer-1 GEMM + el/er (LDS.128, W column in registers) ------
__global__ void k_gemm(const float* __restrict__ x, const float* __restrict__ W) {
    __shared__ float xs[32][IN_F + 4];
    __shared__ float sAl[IN_F][8], sAr[IN_F][8];
    const int tid = threadIdx.x;
    const int n0 = blockIdx.x * 32;
    #pragma unroll
    for (int r = 0; r < 2; ++r) {
        int e = tid + r * 256;
        int n = e >> 4, i4 = e & 15;
        int node = n0 + n;
        float4 v = (node < N_NODES) ? ((const float4*)(x + (size_t)node * IN_F))[i4]
                                    : make_float4(0.f, 0.f, 0.f, 0.f);
        *(float4*)&xs[n][i4 * 4] = v;
    }
    #pragma unroll
    for (int r = 0; r < 2; ++r) {
        int e = tid + r * 256;
        sAl[e >> 3][e & 7] = g_Al[e];
        sAr[e >> 3][e & 7] = g_Ar[e];
    }
    __syncthreads();

    const int c = tid;
    float wreg[IN_F];
    #pragma unroll
    for (int i = 0; i < IN_F; ++i) wreg[i] = W[i * CH + c];

    #pragma unroll 4
    for (int n = 0; n < 32; ++n) {
        const float4* xr = (const float4*)xs[n];
        float a = 0.f;
        #pragma unroll
        for (int i4 = 0; i4 < 16; ++i4) {
            float4 xv = xr[i4];
            a = fmaf(xv.x, wreg[4 * i4 + 0], a);
            a = fmaf(xv.y, wreg[4 * i4 + 1], a);
            a = fmaf(xv.z, wreg[4 * i4 + 2], a);
            a = fmaf(xv.w, wreg[4 * i4 + 3], a);
        }
        int node = n0 + n;
        if (node < N_NODES) g_feat1h[(size_t)node * CH + c] = __float2half_rn(a);
    }

    // el/er: thread t handles (node tid>>3, head tid&7): two 64-wide dots
    const int nn = tid >> 3, h = tid & 7;
    const float4* xr = (const float4*)xs[nn];
    float sl = 0.f, sr = 0.f;
    #pragma unroll
    for (int i4 = 0; i4 < 16; ++i4) {
        float4 xv = xr[i4];
        sl = fmaf(xv.x, sAl[4 * i4 + 0][h], sl); sr = fmaf(xv.x, sAr[4 * i4 + 0][h], sr);
        sl = fmaf(xv.y, sAl[4 * i4 + 1][h], sl); sr = fmaf(xv.y, sAr[4 * i4 + 1][h], sr);
        sl = fmaf(xv.z, sAl[4 * i4 + 2][h], sl); sr = fmaf(xv.z, sAr[4 * i4 + 2][h], sr);
        sl = fmaf(xv.w, sAl[4 * i4 + 3][h], sl); sr = fmaf(xv.w, sAr[4 * i4 + 3][h], sr);
    }
    int node = n0 + nn;
    if (node < N_NODES) {
        g_el1[node * 8 + h] = sl;
        g_er1[node * 8 + h] = sr;
    }
}

// ---------------- layer-1 aggregation (warp per dst, batch-8 + prefetch) -----
__global__ void k_agg1(const float* __restrict__ b1, const float* __restrict__ W2) {
    const int warp = threadIdx.x >> 5, l = threadIdx.x & 31;
    const int n = blockIdx.x * 8 + warp;
    if (n >= N_NODES) return;
    const int h = l >> 2;
    const float er = g_er1[n * 8 + h];
    const int start = g_off[n], cnt = g_deg[n];

    float s = 0.f;
    float acc[8];
    #pragma unroll
    for (int i = 0; i < 8; ++i) acc[i] = 0.f;

    const int co = l << 3;
    int k = 0;
    if (cnt >= 8) {
        int cur[8];
        #pragma unroll
        for (int j = 0; j < 8; ++j) cur[j] = g_csr_src[start + j];
        while (k + 8 <= cnt) {
            float e[8];
            #pragma unroll
            for (int j = 0; j < 8; ++j) e[j] = g_el1[cur[j] * 8 + h];
            uint4 r[8];
            #pragma unroll
            for (int j = 0; j < 8; ++j)
                r[j] = *reinterpret_cast<const uint4*>(g_feat1h + (size_t)cur[j] * CH + co);
            k += 8;
            const bool more = (k + 8 <= cnt);
            if (more) {
                #pragma unroll
                for (int j = 0; j < 8; ++j) cur[j] = g_csr_src[start + k + j];
            }
            float p[8];
            #pragma unroll
            for (int j = 0; j < 8; ++j) {
                float ej = e[j] + er;
                ej = (ej > 0.f) ? ej : NEG * ej;
                p[j] = __expf(ej);
            }
            #pragma unroll
            for (int j = 0; j < 8; ++j) s += p[j];
            #pragma unroll
            for (int j = 0; j < 8; ++j) {
                float2 f0 = __half22float2(*reinterpret_cast<__half2*>(&r[j].x));
                float2 f1 = __half22float2(*reinterpret_cast<__half2*>(&r[j].y));
                float2 f2 = __half22float2(*reinterpret_cast<__half2*>(&r[j].z));
                float2 f3 = __half22float2(*reinterpret_cast<__half2*>(&r[j].w));
                acc[0] = fmaf(p[j], f0.x, acc[0]);
                acc[1] = fmaf(p[j], f0.y, acc[1]);
                acc[2] = fmaf(p[j], f1.x, acc[2]);
                acc[3] = fmaf(p[j], f1.y, acc[3]);
                acc[4] = fmaf(p[j], f2.x, acc[4]);
                acc[5] = fmaf(p[j], f2.y, acc[5]);
                acc[6] = fmaf(p[j], f3.x, acc[6]);
                acc[7] = fmaf(p[j], f3.y, acc[7]);
            }
        }
    }
    for (; k < cnt; ++k) {
        int sn = g_csr_src[start + k];
        float e = g_el1[sn * 8 + h] + er;
        e = (e > 0.f) ? e : NEG * e;
        float p = __expf(e);
        s += p;
        uint4 rr = *reinterpret_cast<const uint4*>(g_feat1h + (size_t)sn * CH + co);
        float2 f0 = __half22float2(*reinterpret_cast<__half2*>(&rr.x));
        float2 f1 = __half22float2(*reinterpret_cast<__half2*>(&rr.y));
        float2 f2 = __half22float2(*reinterpret_cast<__half2*>(&rr.z));
        float2 f3 = __half22float2(*reinterpret_cast<__half2*>(&rr.w));
        acc[0] = fmaf(p, f0.x, acc[0]);
        acc[1] = fmaf(p, f0.y, acc[1]);
        acc[2] = fmaf(p, f1.x, acc[2]);
        acc[3] = fmaf(p, f1.y, acc[3]);
        acc[4] = fmaf(p, f2.x, acc[4]);
        acc[5] = fmaf(p, f2.y, acc[5]);
        acc[6] = fmaf(p, f3.x, acc[6]);
        acc[7] = fmaf(p, f3.y, acc[7]);
    }

    float4 bv0 = *reinterpret_cast<const float4*>(b1 + co);
    float4 bv1 = *reinterpret_cast<const float4*>(b1 + co + 4);
    float4 wv0 = *reinterpret_cast<const float4*>(W2 + co);
    float4 wv1 = *reinterpret_cast<const float4*>(W2 + co + 4);
    const float bb[8] = {bv0.x, bv0.y, bv0.z, bv0.w, bv1.x, bv1.y, bv1.z, bv1.w};
    const float ww[8] = {wv0.x, wv0.y, wv0.z, wv0.w, wv1.x, wv1.y, wv1.z, wv1.w};
    float inv = (cnt > 0) ? 1.f / s : 0.f;
    float dot = 0.f;
    #pragma unroll
    for (int i = 0; i < 8; ++i) {
        float v = acc[i] * inv + bb[i];
        v = fmaxf(v, 0.f);
        dot = fmaf(v, ww[i], dot);
    }
    #pragma unroll
    for (int o = 16; o; o >>= 1) dot += __shfl_xor_sync(0xffffffffu, dot, o);
    if (l == 0) g_feat2[n] = dot;
}

// ---------------- layer-2 aggregation + sigmoid (thread per dst) -------------
__global__ void k_gat2(const float* __restrict__ al2p, const float* __restrict__ ar2p,
                       const float* __restrict__ b2p, float* __restrict__ out) {
    int n = blockIdx.x * blockDim.x + threadIdx.x;
    if (n >= N_NODES) return;
    const float al2 = al2p[0], ar2 = ar2p[0], b2 = b2p[0];
    const float er = g_feat2[n] * ar2;
    const int start = g_off[n], cnt = g_deg[n];
    float s = 0.f, acc = 0.f;
    int k = 0;
    if (cnt >= 4) {
        int cur[4];
        #pragma unroll
        for (int j = 0; j < 4; ++j) cur[j] = g_csr_src[start + j];
        while (k + 4 <= cnt) {
            float f[4];
            #pragma unroll
            for (int j = 0; j < 4; ++j) f[j] = g_feat2[cur[j]];
            k += 4;
            const bool more = (k + 4 <= cnt);
            int nxt[4];
            if (more) {
                #pragma unroll
                for (int j = 0; j < 4; ++j) nxt[j] = g_csr_src[start + k + j];
            }
            #pragma unroll
            for (int j = 0; j < 4; ++j) {
                float e = f[j] * al2 + er;
                e = (e > 0.f) ? e : NEG * e;
                float p = __expf(e);
                s += p;
                acc = fmaf(p, f[j], acc);
            }
            if (more) {
                #pragma unroll
                for (int j = 0; j < 4; ++j) cur[j] = nxt[j];
            }
        }
    }
    for (; k < cnt; ++k) {
        float fs = g_feat2[g_csr_src[start + k]];
        float e = fs * al2 + er;
        e = (e > 0.f) ? e : NEG * e;
        float p = __expf(e);
        s += p;
        acc = fmaf(p, fs, acc);
    }
    float r = (cnt > 0) ? (acc / s + b2) : b2;
    out[n] = 1.f / (1.f + __expf(-r));
}

// ---------------- launch ----------------
extern "C" void kernel_launch(void* const* d_in, const int* in_sizes, int n_in,
                              void* d_out, int out_size) {
    const float* x    = (const float*)d_in[0];   // [N,64]
    const int*   src  = (const int*)  d_in[1];   // [E]
    const int*   dst  = (const int*)  d_in[2];   // [E]
    // d_in[3] edge_types: unused
    const float* W1   = (const float*)d_in[4];   // [64,8,32]
    const float* al1  = (const float*)d_in[5];   // [8,32]
    const float* ar1  = (const float*)d_in[6];   // [8,32]
    const float* b1   = (const float*)d_in[7];   // [8,32]
    const float* W2   = (const float*)d_in[8];   // [256,1,1]
    const float* al2  = (const float*)d_in[9];   // [1,1]
    const float* ar2  = (const float*)d_in[10];  // [1,1]
    const float* b2   = (const float*)d_in[11];  // [1,1]
    float* out = (float*)d_out;                  // [N,1]

    (void)in_sizes; (void)n_in; (void)out_size;

    // CSR build (parallel scan)
    k_zero_deg<<<(N_NODES + 255) / 256, 256>>>();
    k_count<<<(N_EDGES / 4 + 255) / 256, 256>>>(dst);
    k_scan_a<<<NBLK, 256>>>();
    k_scan_b<<<1, 64>>>();
    k_scan_c<<<NBLK, SCAN_B>>>();
    k_fill<<<(N_EDGES / 4 + 255) / 256, 256>>>(src, dst);

    // layer 1
    k_proj<<<1, 512>>>(W1, al1, ar1);
    k_gemm<<<(N_NODES + 31) / 32, 256>>>(x, W1);
    k_agg1<<<(N_NODES + 7) / 8, 256>>>(b1, W2);

    // layer 2
    k_gat2<<<(N_NODES + 255) / 256, 256>>>(al2, ar2, b2, out);
}

// round 16
// speedup vs baseline: 2.2499x; 1.0146x over previous
#include <cuda_runtime.h>
#include <cuda_fp16.h>
#include <math.h>

// Problem constants (fixed by the reference)
#define N_NODES 50000
#define N_EDGES 800000
#define IN_F    64
#define HEADS   8
#define HID     32
#define CH      256          // HEADS*HID
#define NEG     0.2f

#define SCAN_B  1024
#define NBLK    ((N_NODES + SCAN_B - 1) / SCAN_B)   // 49

// ---------------- scratch (no cudaMalloc allowed) ----------------
__device__ __align__(16) __half g_feat1h[(size_t)N_NODES * CH];  // 25.6 MB fp16 gather table
__device__ float g_el1[N_NODES * HEADS];
__device__ float g_er1[N_NODES * HEADS];
__device__ float g_feat2[N_NODES];
__device__ int   g_deg[N_NODES];
__device__ int   g_off[N_NODES];
__device__ int   g_rank[N_EDGES];
__device__ int   g_csr_src[N_EDGES];
__device__ float g_Al[IN_F * HEADS];
__device__ float g_Ar[IN_F * HEADS];
__device__ int   g_bsum[NBLK];

// ---------------- CSR construction ----------------
__global__ void k_zero_deg() {
    int i = blockIdx.x * blockDim.x + threadIdx.x;
    if (i < N_NODES) g_deg[i] = 0;
}

// count degrees AND record each edge's rank within its dst segment
__global__ void k_count(const int* __restrict__ dst) {
    int i = (blockIdx.x * blockDim.x + threadIdx.x) * 4;
    if (i + 3 < N_EDGES) {
        int4 d = *(const int4*)(dst + i);
        int4 r;
        r.x = atomicAdd(&g_deg[d.x], 1);
        r.y = atomicAdd(&g_deg[d.y], 1);
        r.z = atomicAdd(&g_deg[d.z], 1);
        r.w = atomicAdd(&g_deg[d.w], 1);
        *(int4*)(g_rank + i) = r;
    } else {
        for (int e = i; e < N_EDGES; ++e)
            g_rank[e] = atomicAdd(&g_deg[dst[e]], 1);
    }
}

// scan stage A: per-1024-tile degree sums (49 blocks x 256 threads, coalesced)
__global__ void k_scan_a() {
    __shared__ int sh[8];
    const int b = blockIdx.x, t = threadIdx.x;
    const int base = b * SCAN_B;
    int s = 0;
    #pragma unroll
    for (int j = 0; j < 4; ++j) {
        int i = base + t + j * 256;
        if (i < N_NODES) s += g_deg[i];
    }
    #pragma unroll
    for (int o = 16; o; o >>= 1) s += __shfl_down_sync(0xffffffffu, s, o);
    if ((t & 31) == 0) sh[t >> 5] = s;
    __syncthreads();
    if (t < 8) {
        int v = sh[t];
        #pragma unroll
        for (int o = 4; o; o >>= 1) v += __shfl_down_sync(0xffu, v, o, 8);
        if (t == 0) g_bsum[b] = v;
    }
}

// scan stage C: in-block Hillis-Steele; block offset computed inline by warp 0
// (sum of g_bsum[0..b-1], <= 49 values) -> g_off
__global__ void k_scan_c() {
    __shared__ int sh[SCAN_B];
    __shared__ int s_boff;
    const int b = blockIdx.x, t = threadIdx.x;   // 1024 threads
    // warp 0: exclusive block offset = sum of preceding block sums
    if (t < 32) {
        int v = 0;
        if (t < b) v += g_bsum[t];
        if (t + 32 < b) v += g_bsum[t + 32];     // NBLK=49 <= 64
        #pragma unroll
        for (int o = 16; o; o >>= 1) v += __shfl_down_sync(0xffffffffu, v, o);
        if (t == 0) s_boff = v;
    }
    const int i = b * SCAN_B + t;
    int v = (i < N_NODES) ? g_deg[i] : 0;
    sh[t] = v;
    __syncthreads();
    for (int o = 1; o < SCAN_B; o <<= 1) {
        int u = (t >= o) ? sh[t - o] : 0;
        __syncthreads();
        sh[t] += u;
        __syncthreads();
    }
    if (i < N_NODES) g_off[i] = s_boff + sh[t] - v;   // exclusive
}

// non-atomic fill: slot = off[dst] + rank[e] is unique per edge
__global__ void k_fill(const int* __restrict__ src, const int* __restrict__ dst) {
    int i = (blockIdx.x * blockDim.x + threadIdx.x) * 4;
    if (i + 3 < N_EDGES) {
        int4 d = *(const int4*)(dst + i);
        int4 s = *(const int4*)(src + i);
        int4 r = *(const int4*)(g_rank + i);
        g_csr_src[g_off[d.x] + r.x] = s.x;
        g_csr_src[g_off[d.y] + r.y] = s.y;
        g_csr_src[g_off[d.z] + r.z] = s.z;
        g_csr_src[g_off[d.w] + r.w] = s.w;
    } else {
        for (int e = i; e < N_EDGES; ++e)
            g_csr_src[g_off[dst[e]] + g_rank[e]] = src[e];
    }
}

// ---------------- tiny projection: Al = W . al, Ar = W . ar ------------------
__global__ void k_proj(const float* __restrict__ W, const float* __restrict__ al,
                       const float* __restrict__ ar) {
    int t = threadIdx.x;            // 512 threads
    int i = t >> 3, h = t & 7;
    float sl = 0.f, sr = 0.f;
    #pragma unroll 8
    for (int o = 0; o < HID; ++o) {
        float w = W[i * CH + h * HID + o];
        sl = fmaf(w, al[h * HID + o], sl);
        sr = fmaf(w, ar[h * HID + o], sr);
    }
    g_Al[i * 8 + h] = sl;
    g_Ar[i * 8 + h] = sr;
}

// ---------------- layer-1 GEMM + el/er (LDS.128, W column in registers) ------
__global__ void k_gemm(const float* __restrict__ x, const float* __restrict__ W) {
    __shared__ float xs[32][IN_F + 4];
    __shared__ float sAl[IN_F][8], sAr[IN_F][8];
    const int tid = threadIdx.x;
    const int n0 = blockIdx.x * 32;
    #pragma unroll
    for (int r = 0; r < 2; ++r) {
        int e = tid + r * 256;
        int n = e >> 4, i4 = e & 15;
        int node = n0 + n;
        float4 v = (node < N_NODES) ? ((const float4*)(x + (size_t)node * IN_F))[i4]
                                    : make_float4(0.f, 0.f, 0.f, 0.f);
        *(float4*)&xs[n][i4 * 4] = v;
    }
    #pragma unroll
    for (int r = 0; r < 2; ++r) {
        int e = tid + r * 256;
        sAl[e >> 3][e & 7] = g_Al[e];
        sAr[e >> 3][e & 7] = g_Ar[e];
    }
    __syncthreads();

    const int c = tid;
    float wreg[IN_F];
    #pragma unroll
    for (int i = 0; i < IN_F; ++i) wreg[i] = W[i * CH + c];

    #pragma unroll 4
    for (int n = 0; n < 32; ++n) {
        const float4* xr = (const float4*)xs[n];
        float a = 0.f;
        #pragma unroll
        for (int i4 = 0; i4 < 16; ++i4) {
            float4 xv = xr[i4];
            a = fmaf(xv.x, wreg[4 * i4 + 0], a);
            a = fmaf(xv.y, wreg[4 * i4 + 1], a);
            a = fmaf(xv.z, wreg[4 * i4 + 2], a);
            a = fmaf(xv.w, wreg[4 * i4 + 3], a);
        }
        int node = n0 + n;
        if (node < N_NODES) g_feat1h[(size_t)node * CH + c] = __float2half_rn(a);
    }

    // el/er: thread t handles (node tid>>3, head tid&7): two 64-wide dots
    const int nn = tid >> 3, h = tid & 7;
    const float4* xr = (const float4*)xs[nn];
    float sl = 0.f, sr = 0.f;
    #pragma unroll
    for (int i4 = 0; i4 < 16; ++i4) {
        float4 xv = xr[i4];
        sl = fmaf(xv.x, sAl[4 * i4 + 0][h], sl); sr = fmaf(xv.x, sAr[4 * i4 + 0][h], sr);
        sl = fmaf(xv.y, sAl[4 * i4 + 1][h], sl); sr = fmaf(xv.y, sAr[4 * i4 + 1][h], sr);
        sl = fmaf(xv.z, sAl[4 * i4 + 2][h], sl); sr = fmaf(xv.z, sAr[4 * i4 + 2][h], sr);
        sl = fmaf(xv.w, sAl[4 * i4 + 3][h], sl); sr = fmaf(xv.w, sAr[4 * i4 + 3][h], sr);
    }
    int node = n0 + nn;
    if (node < N_NODES) {
        g_el1[node * 8 + h] = sl;
        g_er1[node * 8 + h] = sr;
    }
}

// ---------------- layer-1 aggregation (warp per dst, batch-8 + prefetch) -----
__global__ void k_agg1(const float* __restrict__ b1, const float* __restrict__ W2) {
    const int warp = threadIdx.x >> 5, l = threadIdx.x & 31;
    const int n = blockIdx.x * 8 + warp;
    if (n >= N_NODES) return;
    const int h = l >> 2;
    const float er = g_er1[n * 8 + h];
    const int start = g_off[n], cnt = g_deg[n];

    float s = 0.f;
    float acc[8];
    #pragma unroll
    for (int i = 0; i < 8; ++i) acc[i] = 0.f;

    const int co = l << 3;
    int k = 0;
    if (cnt >= 8) {
        int cur[8];
        #pragma unroll
        for (int j = 0; j < 8; ++j) cur[j] = g_csr_src[start + j];
        while (k + 8 <= cnt) {
            float e[8];
            #pragma unroll
            for (int j = 0; j < 8; ++j) e[j] = g_el1[cur[j] * 8 + h];
            uint4 r[8];
            #pragma unroll
            for (int j = 0; j < 8; ++j)
                r[j] = *reinterpret_cast<const uint4*>(g_feat1h + (size_t)cur[j] * CH + co);
            k += 8;
            const bool more = (k + 8 <= cnt);
            if (more) {
                #pragma unroll
                for (int j = 0; j < 8; ++j) cur[j] = g_csr_src[start + k + j];
            }
            float p[8];
            #pragma unroll
            for (int j = 0; j < 8; ++j) {
                float ej = e[j] + er;
                ej = (ej > 0.f) ? ej : NEG * ej;
                p[j] = __expf(ej);
            }
            #pragma unroll
            for (int j = 0; j < 8; ++j) s += p[j];
            #pragma unroll
            for (int j = 0; j < 8; ++j) {
                float2 f0 = __half22float2(*reinterpret_cast<__half2*>(&r[j].x));
                float2 f1 = __half22float2(*reinterpret_cast<__half2*>(&r[j].y));
                float2 f2 = __half22float2(*reinterpret_cast<__half2*>(&r[j].z));
                float2 f3 = __half22float2(*reinterpret_cast<__half2*>(&r[j].w));
                acc[0] = fmaf(p[j], f0.x, acc[0]);
                acc[1] = fmaf(p[j], f0.y, acc[1]);
                acc[2] = fmaf(p[j], f1.x, acc[2]);
                acc[3] = fmaf(p[j], f1.y, acc[3]);
                acc[4] = fmaf(p[j], f2.x, acc[4]);
                acc[5] = fmaf(p[j], f2.y, acc[5]);
                acc[6] = fmaf(p[j], f3.x, acc[6]);
                acc[7] = fmaf(p[j], f3.y, acc[7]);
            }
        }
    }
    for (; k < cnt; ++k) {
        int sn = g_csr_src[start + k];
        float e = g_el1[sn * 8 + h] + er;
        e = (e > 0.f) ? e : NEG * e;
        float p = __expf(e);
        s += p;
        uint4 rr = *reinterpret_cast<const uint4*>(g_feat1h + (size_t)sn * CH + co);
        float2 f0 = __half22float2(*reinterpret_cast<__half2*>(&rr.x));
        float2 f1 = __half22float2(*reinterpret_cast<__half2*>(&rr.y));
        float2 f2 = __half22float2(*reinterpret_cast<__half2*>(&rr.z));
        float2 f3 = __half22float2(*reinterpret_cast<__half2*>(&rr.w));
        acc[0] = fmaf(p, f0.x, acc[0]);
        acc[1] = fmaf(p, f0.y, acc[1]);
        acc[2] = fmaf(p, f1.x, acc[2]);
        acc[3] = fmaf(p, f1.y, acc[3]);
        acc[4] = fmaf(p, f2.x, acc[4]);
        acc[5] = fmaf(p, f2.y, acc[5]);
        acc[6] = fmaf(p, f3.x, acc[6]);
        acc[7] = fmaf(p, f3.y, acc[7]);
    }

    float4 bv0 = *reinterpret_cast<const float4*>(b1 + co);
    float4 bv1 = *reinterpret_cast<const float4*>(b1 + co + 4);
    float4 wv0 = *reinterpret_cast<const float4*>(W2 + co);
    float4 wv1 = *reinterpret_cast<const float4*>(W2 + co + 4);
    const float bb[8] = {bv0.x, bv0.y, bv0.z, bv0.w, bv1.x, bv1.y, bv1.z, bv1.w};
    const float ww[8] = {wv0.x, wv0.y, wv0.z, wv0.w, wv1.x, wv1.y, wv1.z, wv1.w};
    float inv = (cnt > 0) ? 1.f / s : 0.f;
    float dot = 0.f;
    #pragma unroll
    for (int i = 0; i < 8; ++i) {
        float v = acc[i] * inv + bb[i];
        v = fmaxf(v, 0.f);
        dot = fmaf(v, ww[i], dot);
    }
    #pragma unroll
    for (int o = 16; o; o >>= 1) dot += __shfl_xor_sync(0xffffffffu, dot, o);
    if (l == 0) g_feat2[n] = dot;
}

// ---------------- layer-2 aggregation + sigmoid (thread per dst) -------------
__global__ void k_gat2(const float* __restrict__ al2p, const float* __restrict__ ar2p,
                       const float* __restrict__ b2p, float* __restrict__ out) {
    int n = blockIdx.x * blockDim.x + threadIdx.x;
    if (n >= N_NODES) return;
    const float al2 = al2p[0], ar2 = ar2p[0], b2 = b2p[0];
    const float er = g_feat2[n] * ar2;
    const int start = g_off[n], cnt = g_deg[n];
    float s = 0.f, acc = 0.f;
    int k = 0;
    if (cnt >= 4) {
        int cur[4];
        #pragma unroll
        for (int j = 0; j < 4; ++j) cur[j] = g_csr_src[start + j];
        while (k + 4 <= cnt) {
            float f[4];
            #pragma unroll
            for (int j = 0; j < 4; ++j) f[j] = g_feat2[cur[j]];
            k += 4;
            const bool more = (k + 4 <= cnt);
            int nxt[4];
            if (more) {
                #pragma unroll
                for (int j = 0; j < 4; ++j) nxt[j] = g_csr_src[start + k + j];
            }
            #pragma unroll
            for (int j = 0; j < 4; ++j) {
                float e = f[j] * al2 + er;
                e = (e > 0.f) ? e : NEG * e;
                float p = __expf(e);
                s += p;
                acc = fmaf(p, f[j], acc);
            }
            if (more) {
                #pragma unroll
                for (int j = 0; j < 4; ++j) cur[j] = nxt[j];
            }
        }
    }
    for (; k < cnt; ++k) {
        float fs = g_feat2[g_csr_src[start + k]];
        float e = fs * al2 + er;
        e = (e > 0.f) ? e : NEG * e;
        float p = __expf(e);
        s += p;
        acc = fmaf(p, fs, acc);
    }
    float r = (cnt > 0) ? (acc / s + b2) : b2;
    out[n] = 1.f / (1.f + __expf(-r));
}

// ---------------- launch ----------------
extern "C" void kernel_launch(void* const* d_in, const int* in_sizes, int n_in,
                              void* d_out, int out_size) {
    const float* x    = (const float*)d_in[0];   // [N,64]
    const int*   src  = (const int*)  d_in[1];   // [E]
    const int*   dst  = (const int*)  d_in[2];   // [E]
    // d_in[3] edge_types: unused
    const float* W1   = (const float*)d_in[4];   // [64,8,32]
    const float* al1  = (const float*)d_in[5];   // [8,32]
    const float* ar1  = (const float*)d_in[6];   // [8,32]
    const float* b1   = (const float*)d_in[7];   // [8,32]
    const float* W2   = (const float*)d_in[8];   // [256,1,1]
    const float* al2  = (const float*)d_in[9];   // [1,1]
    const float* ar2  = (const float*)d_in[10];  // [1,1]
    const float* b2   = (const float*)d_in[11];  // [1,1]
    float* out = (float*)d_out;                  // [N,1]

    (void)in_sizes; (void)n_in; (void)out_size;

    // CSR build (parallel scan; scan_b folded into scan_c)
    k_zero_deg<<<(N_NODES + 255) / 256, 256>>>();
    k_count<<<(N_EDGES / 4 + 255) / 256, 256>>>(dst);
    k_scan_a<<<NBLK, 256>>>();
    k_scan_c<<<NBLK, SCAN_B>>>();
    k_fill<<<(N_EDGES / 4 + 255) / 256, 256>>>(src, dst);

    // layer 1
    k_proj<<<1, 512>>>(W1, al1, ar1);
    k_gemm<<<(N_NODES + 31) / 32, 256>>>(x, W1);
    k_agg1<<<(N_NODES + 7) / 8, 256>>>(b1, W2);

    // layer 2
    k_gat2<<<(N_NODES + 255) / 256, 256>>>(al2, ar2, b2, out);
}

// round 17
// speedup vs baseline: 2.5743x; 1.1442x over previous
#include <cuda_runtime.h>
#include <cuda_fp16.h>
#include <math.h>

// Problem constants (fixed by the reference)
#define N_NODES 50000
#define N_EDGES 800000
#define IN_F    64
#define HEADS   8
#define HID     32
#define CH      256          // HEADS*HID
#define NEG     0.2f

#define SCAN_B  1024
#define NBLK    ((N_NODES + SCAN_B - 1) / SCAN_B)   // 49

// ---------------- scratch (no cudaMalloc allowed) ----------------
__device__ __align__(16) __half g_feat1h[(size_t)N_NODES * CH];  // 25.6 MB fp16 gather table
__device__ float g_el1[N_NODES * HEADS];
__device__ float g_er1[N_NODES * HEADS];
__device__ float g_feat2[N_NODES];
__device__ int   g_deg[N_NODES];
__device__ int   g_off[N_NODES];
__device__ int   g_rank[N_EDGES];
__device__ int   g_csr_src[N_EDGES];
__device__ float g_Al[IN_F * HEADS];
__device__ float g_Ar[IN_F * HEADS];
__device__ __align__(16) __half g_Wh[IN_F * CH];     // fp16 copy of W1
__device__ int   g_bsum[NBLK];

// ---------------- CSR construction ----------------
__global__ void k_zero_deg() {
    int i = blockIdx.x * blockDim.x + threadIdx.x;
    if (i < N_NODES) g_deg[i] = 0;
}

// count degrees AND record each edge's rank within its dst segment
__global__ void k_count(const int* __restrict__ dst) {
    int i = (blockIdx.x * blockDim.x + threadIdx.x) * 4;
    if (i + 3 < N_EDGES) {
        int4 d = *(const int4*)(dst + i);
        int4 r;
        r.x = atomicAdd(&g_deg[d.x], 1);
        r.y = atomicAdd(&g_deg[d.y], 1);
        r.z = atomicAdd(&g_deg[d.z], 1);
        r.w = atomicAdd(&g_deg[d.w], 1);
        *(int4*)(g_rank + i) = r;
    } else {
        for (int e = i; e < N_EDGES; ++e)
            g_rank[e] = atomicAdd(&g_deg[dst[e]], 1);
    }
}

// scan stage A: per-1024-tile degree sums (49 blocks x 256 threads, coalesced)
__global__ void k_scan_a() {
    __shared__ int sh[8];
    const int b = blockIdx.x, t = threadIdx.x;
    const int base = b * SCAN_B;
    int s = 0;
    #pragma unroll
    for (int j = 0; j < 4; ++j) {
        int i = base + t + j * 256;
        if (i < N_NODES) s += g_deg[i];
    }
    #pragma unroll
    for (int o = 16; o; o >>= 1) s += __shfl_down_sync(0xffffffffu, s, o);
    if ((t & 31) == 0) sh[t >> 5] = s;
    __syncthreads();
    if (t < 8) {
        int v = sh[t];
        #pragma unroll
        for (int o = 4; o; o >>= 1) v += __shfl_down_sync(0xffu, v, o, 8);
        if (t == 0) g_bsum[b] = v;
    }
}

// scan stage C: in-block Hillis-Steele; block offset computed inline by warp 0
__global__ void k_scan_c() {
    __shared__ int sh[SCAN_B];
    __shared__ int s_boff;
    const int b = blockIdx.x, t = threadIdx.x;   // 1024 threads
    if (t < 32) {
        int v = 0;
        if (t < b) v += g_bsum[t];
        if (t + 32 < b) v += g_bsum[t + 32];     // NBLK=49 <= 64
        #pragma unroll
        for (int o = 16; o; o >>= 1) v += __shfl_down_sync(0xffffffffu, v, o);
        if (t == 0) s_boff = v;
    }
    const int i = b * SCAN_B + t;
    int v = (i < N_NODES) ? g_deg[i] : 0;
    sh[t] = v;
    __syncthreads();
    for (int o = 1; o < SCAN_B; o <<= 1) {
        int u = (t >= o) ? sh[t - o] : 0;
        __syncthreads();
        sh[t] += u;
        __syncthreads();
    }
    if (i < N_NODES) g_off[i] = s_boff + sh[t] - v;   // exclusive
}

// non-atomic fill: slot = off[dst] + rank[e] is unique per edge
__global__ void k_fill(const int* __restrict__ src, const int* __restrict__ dst) {
    int i = (blockIdx.x * blockDim.x + threadIdx.x) * 4;
    if (i + 3 < N_EDGES) {
        int4 d = *(const int4*)(dst + i);
        int4 s = *(const int4*)(src + i);
        int4 r = *(const int4*)(g_rank + i);
        g_csr_src[g_off[d.x] + r.x] = s.x;
        g_csr_src[g_off[d.y] + r.y] = s.y;
        g_csr_src[g_off[d.z] + r.z] = s.z;
        g_csr_src[g_off[d.w] + r.w] = s.w;
    } else {
        for (int e = i; e < N_EDGES; ++e)
            g_csr_src[g_off[dst[e]] + g_rank[e]] = src[e];
    }
}

// ---------------- projection + W fp16 conversion -----------------------------
// Al = W.al, Ar = W.ar; also convert W to fp16 table g_Wh.
__global__ void k_proj(const float* __restrict__ W, const float* __restrict__ al,
                       const float* __restrict__ ar) {
    int t = threadIdx.x;            // 512 threads
    int i = t >> 3, h = t & 7;
    float sl = 0.f, sr = 0.f;
    #pragma unroll 8
    for (int o = 0; o < HID; ++o) {
        float w = W[i * CH + h * HID + o];
        sl = fmaf(w, al[h * HID + o], sl);
        sr = fmaf(w, ar[h * HID + o], sr);
    }
    g_Al[i * 8 + h] = sl;
    g_Ar[i * 8 + h] = sr;
    // fp16 copy of W (16384 halves, 32 per thread, coalesced)
    #pragma unroll
    for (int j = 0; j < 32; ++j) {
        int idx = t + j * 512;
        g_Wh[idx] = __float2half_rn(W[idx]);
    }
}

// ---------------- layer-1 GEMM + el/er (HFMA2 packed node-pairs) -------------
// 256 threads (one output channel each), 32 nodes per block.
// Node pair (n16, n16+16) packed into half2 lanes; 2 FMAs per HFMA2 issue.
// el/er stay fp32 (exact logits).
__global__ void k_gemm(const float* __restrict__ x) {
    __shared__ float xs[32][IN_F + 4];
    __shared__ __align__(16) __half2 xp[IN_F][16];   // [i][n16] = (x[n16][i], x[n16+16][i])
    __shared__ float sAl[IN_F][8], sAr[IN_F][8];
    const int tid = threadIdx.x;
    const int n0 = blockIdx.x * 32;
    #pragma unroll
    for (int r = 0; r < 2; ++r) {
        int e = tid + r * 256;
        int n = e >> 4, i4 = e & 15;
        int node = n0 + n;
        float4 v = (node < N_NODES) ? ((const float4*)(x + (size_t)node * IN_F))[i4]
                                    : make_float4(0.f, 0.f, 0.f, 0.f);
        *(float4*)&xs[n][i4 * 4] = v;
    }
    #pragma unroll
    for (int r = 0; r < 2; ++r) {
        int e = tid + r * 256;
        sAl[e >> 3][e & 7] = g_Al[e];
        sAr[e >> 3][e & 7] = g_Ar[e];
    }
    __syncthreads();

    // build packed node-pair table
    #pragma unroll
    for (int r = 0; r < 4; ++r) {
        int e = tid + r * 256;          // 0..1023 : i = e>>4, n16 = e&15
        int i = e >> 4, n = e & 15;
        xp[i][n] = __floats2half2_rn(xs[n][i], xs[n + 16][i]);
    }
    __syncthreads();

    const int c = tid;
    // preload fp16 W column, packed 2 per register
    __half2 wp[32];
    #pragma unroll
    for (int i2 = 0; i2 < 32; ++i2) {
        __half w0 = g_Wh[(2 * i2) * CH + c];
        __half w1 = g_Wh[(2 * i2 + 1) * CH + c];
        wp[i2] = __halves2half2(w0, w1);
    }

    __half2 acc[16];
    #pragma unroll
    for (int q = 0; q < 16; ++q) acc[q] = __float2half2_rn(0.f);

    #pragma unroll 8
    for (int i = 0; i < IN_F; ++i) {
        __half ws = (i & 1) ? __high2half(wp[i >> 1]) : __low2half(wp[i >> 1]);
        __half2 w2 = __half2half2(ws);
        const float4* xr = (const float4*)&xp[i][0];   // 4x LDS.128 broadcast
        #pragma unroll
        for (int q = 0; q < 4; ++q) {
            float4 v = xr[q];
            const __half2* hh = (const __half2*)&v;
            acc[q * 4 + 0] = __hfma2(hh[0], w2, acc[q * 4 + 0]);
            acc[q * 4 + 1] = __hfma2(hh[1], w2, acc[q * 4 + 1]);
            acc[q * 4 + 2] = __hfma2(hh[2], w2, acc[q * 4 + 2]);
            acc[q * 4 + 3] = __hfma2(hh[3], w2, acc[q * 4 + 3]);
        }
    }

    // store fp16 feats (accumulator halves are the outputs)
    #pragma unroll
    for (int n = 0; n < 16; ++n) {
        int node0 = n0 + n, node1 = n0 + n + 16;
        if (node0 < N_NODES) g_feat1h[(size_t)node0 * CH + c] = __low2half(acc[n]);
        if (node1 < N_NODES) g_feat1h[(size_t)node1 * CH + c] = __high2half(acc[n]);
    }

    // el/er: thread t handles (node tid>>3, head tid&7): two 64-wide fp32 dots
    const int nn = tid >> 3, h = tid & 7;
    const float4* xr = (const float4*)xs[nn];
    float sl = 0.f, sr = 0.f;
    #pragma unroll
    for (int i4 = 0; i4 < 16; ++i4) {
        float4 xv = xr[i4];
        sl = fmaf(xv.x, sAl[4 * i4 + 0][h], sl); sr = fmaf(xv.x, sAr[4 * i4 + 0][h], sr);
        sl = fmaf(xv.y, sAl[4 * i4 + 1][h], sl); sr = fmaf(xv.y, sAr[4 * i4 + 1][h], sr);
        sl = fmaf(xv.z, sAl[4 * i4 + 2][h], sl); sr = fmaf(xv.z, sAr[4 * i4 + 2][h], sr);
        sl = fmaf(xv.w, sAl[4 * i4 + 3][h], sl); sr = fmaf(xv.w, sAr[4 * i4 + 3][h], sr);
    }
    int node = n0 + nn;
    if (node < N_NODES) {
        g_el1[node * 8 + h] = sl;
        g_er1[node * 8 + h] = sr;
    }
}

// ---------------- layer-1 aggregation (warp per dst, batch-8 + prefetch) -----
__global__ void k_agg1(const float* __restrict__ b1, const float* __restrict__ W2) {
    const int warp = threadIdx.x >> 5, l = threadIdx.x & 31;
    const int n = blockIdx.x * 8 + warp;
    if (n >= N_NODES) return;
    const int h = l >> 2;
    const float er = g_er1[n * 8 + h];
    const int start = g_off[n], cnt = g_deg[n];

    float s = 0.f;
    float acc[8];
    #pragma unroll
    for (int i = 0; i < 8; ++i) acc[i] = 0.f;

    const int co = l << 3;
    int k = 0;
    if (cnt >= 8) {
        int cur[8];
        #pragma unroll
        for (int j = 0; j < 8; ++j) cur[j] = g_csr_src[start + j];
        while (k + 8 <= cnt) {
            float e[8];
            #pragma unroll
            for (int j = 0; j < 8; ++j) e[j] = g_el1[cur[j] * 8 + h];
            uint4 r[8];
            #pragma unroll
            for (int j = 0; j < 8; ++j)
                r[j] = *reinterpret_cast<const uint4*>(g_feat1h + (size_t)cur[j] * CH + co);
            k += 8;
            const bool more = (k + 8 <= cnt);
            if (more) {
                #pragma unroll
                for (int j = 0; j < 8; ++j) cur[j] = g_csr_src[start + k + j];
            }
            float p[8];
            #pragma unroll
            for (int j = 0; j < 8; ++j) {
                float ej = e[j] + er;
                ej = (ej > 0.f) ? ej : NEG * ej;
                p[j] = __expf(ej);
            }
            #pragma unroll
            for (int j = 0; j < 8; ++j) s += p[j];
            #pragma unroll
            for (int j = 0; j < 8; ++j) {
                float2 f0 = __half22float2(*reinterpret_cast<__half2*>(&r[j].x));
                float2 f1 = __half22float2(*reinterpret_cast<__half2*>(&r[j].y));
                float2 f2 = __half22float2(*reinterpret_cast<__half2*>(&r[j].z));
                float2 f3 = __half22float2(*reinterpret_cast<__half2*>(&r[j].w));
                acc[0] = fmaf(p[j], f0.x, acc[0]);
                acc[1] = fmaf(p[j], f0.y, acc[1]);
                acc[2] = fmaf(p[j], f1.x, acc[2]);
                acc[3] = fmaf(p[j], f1.y, acc[3]);
                acc[4] = fmaf(p[j], f2.x, acc[4]);
                acc[5] = fmaf(p[j], f2.y, acc[5]);
                acc[6] = fmaf(p[j], f3.x, acc[6]);
                acc[7] = fmaf(p[j], f3.y, acc[7]);
            }
        }
    }
    for (; k < cnt; ++k) {
        int sn = g_csr_src[start + k];
        float e = g_el1[sn * 8 + h] + er;
        e = (e > 0.f) ? e : NEG * e;
        float p = __expf(e);
        s += p;
        uint4 rr = *reinterpret_cast<const uint4*>(g_feat1h + (size_t)sn * CH + co);
        float2 f0 = __half22float2(*reinterpret_cast<__half2*>(&rr.x));
        float2 f1 = __half22float2(*reinterpret_cast<__half2*>(&rr.y));
        float2 f2 = __half22float2(*reinterpret_cast<__half2*>(&rr.z));
        float2 f3 = __half22float2(*reinterpret_cast<__half2*>(&rr.w));
        acc[0] = fmaf(p, f0.x, acc[0]);
        acc[1] = fmaf(p, f0.y, acc[1]);
        acc[2] = fmaf(p, f1.x, acc[2]);
        acc[3] = fmaf(p, f1.y, acc[3]);
        acc[4] = fmaf(p, f2.x, acc[4]);
        acc[5] = fmaf(p, f2.y, acc[5]);
        acc[6] = fmaf(p, f3.x, acc[6]);
        acc[7] = fmaf(p, f3.y, acc[7]);
    }

    float4 bv0 = *reinterpret_cast<const float4*>(b1 + co);
    float4 bv1 = *reinterpret_cast<const float4*>(b1 + co + 4);
    float4 wv0 = *reinterpret_cast<const float4*>(W2 + co);
    float4 wv1 = *reinterpret_cast<const float4*>(W2 + co + 4);
    const float bb[8] = {bv0.x, bv0.y, bv0.z, bv0.w, bv1.x, bv1.y, bv1.z, bv1.w};
    const float ww[8] = {wv0.x, wv0.y, wv0.z, wv0.w, wv1.x, wv1.y, wv1.z, wv1.w};
    float inv = (cnt > 0) ? 1.f / s : 0.f;
    float dot = 0.f;
    #pragma unroll
    for (int i = 0; i < 8; ++i) {
        float v = acc[i] * inv + bb[i];
        v = fmaxf(v, 0.f);
        dot = fmaf(v, ww[i], dot);
    }
    #pragma unroll
    for (int o = 16; o; o >>= 1) dot += __shfl_xor_sync(0xffffffffu, dot, o);
    if (l == 0) g_feat2[n] = dot;
}

// ---------------- layer-2 aggregation + sigmoid (thread per dst) -------------
__global__ void k_gat2(const float* __restrict__ al2p, const float* __restrict__ ar2p,
                       const float* __restrict__ b2p, float* __restrict__ out) {
    int n = blockIdx.x * blockDim.x + threadIdx.x;
    if (n >= N_NODES) return;
    const float al2 = al2p[0], ar2 = ar2p[0], b2 = b2p[0];
    const float er = g_feat2[n] * ar2;
    const int start = g_off[n], cnt = g_deg[n];
    float s = 0.f, acc = 0.f;
    int k = 0;
    if (cnt >= 4) {
        int cur[4];
        #pragma unroll
        for (int j = 0; j < 4; ++j) cur[j] = g_csr_src[start + j];
        while (k + 4 <= cnt) {
            float f[4];
            #pragma unroll
            for (int j = 0; j < 4; ++j) f[j] = g_feat2[cur[j]];
            k += 4;
            const bool more = (k + 4 <= cnt);
            int nxt[4];
            if (more) {
                #pragma unroll
                for (int j = 0; j < 4; ++j) nxt[j] = g_csr_src[start + k + j];
            }
            #pragma unroll
            for (int j = 0; j < 4; ++j) {
                float e = f[j] * al2 + er;
                e = (e > 0.f) ? e : NEG * e;
                float p = __expf(e);
                s += p;
                acc = fmaf(p, f[j], acc);
            }
            if (more) {
                #pragma unroll
                for (int j = 0; j < 4; ++j) cur[j] = nxt[j];
            }
        }
    }
    for (; k < cnt; ++k) {
        float fs = g_feat2[g_csr_src[start + k]];
        float e = fs * al2 + er;
        e = (e > 0.f) ? e : NEG * e;
        float p = __expf(e);
        s += p;
        acc = fmaf(p, fs, acc);
    }
    float r = (cnt > 0) ? (acc / s + b2) : b2;
    out[n] = 1.f / (1.f + __expf(-r));
}

// ---------------- launch ----------------
extern "C" void kernel_launch(void* const* d_in, const int* in_sizes, int n_in,
                              void* d_out, int out_size) {
    const float* x    = (const float*)d_in[0];   // [N,64]
    const int*   src  = (const int*)  d_in[1];   // [E]
    const int*   dst  = (const int*)  d_in[2];   // [E]
    // d_in[3] edge_types: unused
    const float* W1   = (const float*)d_in[4];   // [64,8,32]
    const float* al1  = (const float*)d_in[5];   // [8,32]
    const float* ar1  = (const float*)d_in[6];   // [8,32]
    const float* b1   = (const float*)d_in[7];   // [8,32]
    const float* W2   = (const float*)d_in[8];   // [256,1,1]
    const float* al2  = (const float*)d_in[9];   // [1,1]
    const float* ar2  = (const float*)d_in[10];  // [1,1]
    const float* b2   = (const float*)d_in[11];  // [1,1]
    float* out = (float*)d_out;                  // [N,1]

    (void)in_sizes; (void)n_in; (void)out_size;

    // CSR build (parallel scan; scan_b folded into scan_c)
    k_zero_deg<<<(N_NODES + 255) / 256, 256>>>();
    k_count<<<(N_EDGES / 4 + 255) / 256, 256>>>(dst);
    k_scan_a<<<NBLK, 256>>>();
    k_scan_c<<<NBLK, SCAN_B>>>();
    k_fill<<<(N_EDGES / 4 + 255) / 256, 256>>>(src, dst);

    // layer 1
    k_proj<<<1, 512>>>(W1, al1, ar1);
    k_gemm<<<(N_NODES + 31) / 32, 256>>>(x);
    k_agg1<<<(N_NODES + 7) / 8, 256>>>(b1, W2);

    // layer 2
    k_gat2<<<(N_NODES + 255) / 256, 256>>>(al2, ar2, b2, out);
}